// round 4
// baseline (speedup 1.0000x reference)
#include <cuda_runtime.h>
#include <cuda_bf16.h>
#include <stdint.h>

#define DI __device__ __forceinline__

constexpr float SIG_SCALE = 0.125f;             // 1/sqrt(64)
constexpr float SIG_BIAS  = -7.6246189861594f;  // -log(2048)

// ---------------- scratch (static device globals; no allocation) ----------------
#define SCR_ELEMS (4u * 8u * 2048u * 64u)  // 4,194,304
__device__ __align__(16) __nv_bfloat16 g_qhi[SCR_ELEMS];
__device__ __align__(16) __nv_bfloat16 g_qlo[SCR_ELEMS];
__device__ __align__(16) __nv_bfloat16 g_khi[SCR_ELEMS];
__device__ __align__(16) __nv_bfloat16 g_klo[SCR_ELEMS];
__device__ __align__(16) __nv_bfloat16 g_vhi[SCR_ELEMS];  // V^T: [B,H,D,S]
__device__ __align__(16) __nv_bfloat16 g_vlo[SCR_ELEMS];
__device__ __align__(16) __nv_bfloat16 g_ohi[SCR_ELEMS];  // AO: [8192, 512]
__device__ __align__(16) __nv_bfloat16 g_olo[SCR_ELEMS];
__device__ __align__(16) __nv_bfloat16 g_xhi[SCR_ELEMS];  // x split: [8192, 512]
__device__ __align__(16) __nv_bfloat16 g_xlo[SCR_ELEMS];
__device__ __align__(16) __nv_bfloat16 g_whi[4u * 512u * 512u];  // Wq,Wk,Wv,Wo split
__device__ __align__(16) __nv_bfloat16 g_wlo[4u * 512u * 512u];

// ---------------- helpers ----------------
DI uint32_t smem_u32(const void* p) {
    uint32_t a;
    asm("{ .reg .u64 t; cvta.to.shared.u64 t, %1; cvt.u32.u64 %0, t; }" : "=r"(a) : "l"(p));
    return a;
}
DI void ldsm4(uint32_t* r, uint32_t a) {
    asm volatile("ldmatrix.sync.aligned.m8n8.x4.shared.b16 {%0,%1,%2,%3}, [%4];"
                 : "=r"(r[0]), "=r"(r[1]), "=r"(r[2]), "=r"(r[3]) : "r"(a));
}
DI void mma_bf(float* c, const uint32_t* a, const uint32_t* b) {
    asm volatile(
        "mma.sync.aligned.m16n8k16.row.col.f32.bf16.bf16.f32 "
        "{%0,%1,%2,%3}, {%4,%5,%6,%7}, {%8,%9}, {%0,%1,%2,%3};"
        : "+f"(c[0]), "+f"(c[1]), "+f"(c[2]), "+f"(c[3])
        : "r"(a[0]), "r"(a[1]), "r"(a[2]), "r"(a[3]), "r"(b[0]), "r"(b[1]));
}
DI void cp16(uint32_t dst, const void* src) {
    asm volatile("cp.async.cg.shared.global [%0], [%1], 16;" :: "r"(dst), "l"(src));
}
DI void cp_commit() { asm volatile("cp.async.commit_group;" ::: "memory"); }
template <int N> DI void cp_wait() { asm volatile("cp.async.wait_group %0;" :: "n"(N) : "memory"); }

DI void split_s(float f, __nv_bfloat16& h, __nv_bfloat16& l) {
    h = __float2bfloat16_rn(f);
    l = __float2bfloat16_rn(f - __bfloat162float(h));
}
DI void splitpack(float f0, float f1, uint32_t& ph, uint32_t& pl) {
    __nv_bfloat162 vh, vl;
    vh.x = __float2bfloat16_rn(f0);
    vh.y = __float2bfloat16_rn(f1);
    vl.x = __float2bfloat16_rn(f0 - __bfloat162float(vh.x));
    vl.y = __float2bfloat16_rn(f1 - __bfloat162float(vh.y));
    ph = *reinterpret_cast<uint32_t*>(&vh);
    pl = *reinterpret_cast<uint32_t*>(&vl);
}

// =====================================================================
// Kernel 0: pre-split x and weights into bf16 hi/lo global buffers.
// index space: 1,048,576 float4 (x) + 4*65,536 float4 (W's)
// =====================================================================
__global__ __launch_bounds__(256) void k_split(const float* __restrict__ x,
                                               const float* __restrict__ Wq,
                                               const float* __restrict__ Wk,
                                               const float* __restrict__ Wv,
                                               const float* __restrict__ Wo) {
    size_t idx = (size_t)blockIdx.x * 256 + threadIdx.x;
    const float* src;
    __nv_bfloat16 *dh, *dl;
    size_t off;
    if (idx < 1048576) {
        src = x; dh = g_xhi; dl = g_xlo; off = idx;
    } else {
        size_t r = idx - 1048576;
        int ws = (int)(r >> 16);
        off = r & 65535;
        src = (ws == 0) ? Wq : (ws == 1) ? Wk : (ws == 2) ? Wv : Wo;
        dh = g_whi + (size_t)ws * 262144;
        dl = g_wlo + (size_t)ws * 262144;
    }
    float4 f = ((const float4*)src)[off];
    uint32_t h01, l01, h23, l23;
    splitpack(f.x, f.y, h01, l01);
    splitpack(f.z, f.w, h23, l23);
    ((uint2*)dh)[off] = make_uint2(h01, h23);
    ((uint2*)dl)[off] = make_uint2(l01, l23);
}

// =====================================================================
// Shared GEMM machinery: BM=128 BN=128 BK=32, 256 thr (4m x 2n warps),
// split-bf16 3-combo, cp.async double-buffered.
// =====================================================================
constexpr int AST = 40;                      // padded smem row stride (elems)
constexpr int GST_EL = 4 * 128 * AST;        // elems per stage = 20480
constexpr int GEMM_SMEM = 2 * GST_EL * 2;    // bytes = 81920

struct GemmBody {
    template <typename EPI>
    static DI void run(const __nv_bfloat16* Ah, const __nv_bfloat16* Al,
                       const __nv_bfloat16* Bh, const __nv_bfloat16* Bl,
                       int m0, int n0, EPI epi) {
        extern __shared__ __nv_bfloat16 dsm[];
        const uint32_t u0 = smem_u32(dsm);
        const int tid = threadIdx.x, lid = tid & 31, w = tid >> 5;
        const int wm = w >> 1, wn = w & 1;

        auto load_stage = [&](int c, int s) {
            uint32_t base = u0 + (uint32_t)(s * GST_EL * 2);
#pragma unroll
            for (int it = 0; it < 2; it++) {
                int ch = tid + it * 256, r = ch >> 2, q = ch & 3;
                size_t sA = (size_t)(m0 + r) * 512 + c * 32 + q * 8;
                size_t sB = (size_t)(n0 + r) * 512 + c * 32 + q * 8;
                uint32_t d = (uint32_t)((r * AST + q * 8) * 2);
                cp16(base + d, Ah + sA);
                cp16(base + 10240 + d, Al + sA);
                cp16(base + 20480 + d, Bh + sB);
                cp16(base + 30720 + d, Bl + sB);
            }
        };

        float acc[2][8][4];
#pragma unroll
        for (int mf = 0; mf < 2; mf++)
#pragma unroll
            for (int nf = 0; nf < 8; nf++)
#pragma unroll
                for (int e = 0; e < 4; e++) acc[mf][nf][e] = 0.0f;

        load_stage(0, 0);
        cp_commit();
        for (int c = 0; c < 16; c++) {
            const int s = c & 1;
            __syncthreads();
            if (c < 15) {
                load_stage(c + 1, s ^ 1);
                cp_commit();
                cp_wait<1>();
            } else {
                cp_wait<0>();
            }
            __syncthreads();

            const uint32_t bA = u0 + (uint32_t)(s * GST_EL * 2);
            const uint32_t sAh = bA, sAl = bA + 10240, sBh = bA + 20480, sBl = bA + 30720;

            uint32_t ah[2][2][4], al[2][2][4];
#pragma unroll
            for (int mf = 0; mf < 2; mf++)
#pragma unroll
                for (int kk = 0; kk < 2; kk++) {
                    uint32_t off = (uint32_t)(((wm * 32 + mf * 16 + (lid & 15)) * AST +
                                               kk * 16 + (lid >> 4) * 8) * 2);
                    ldsm4(ah[mf][kk], sAh + off);
                    ldsm4(al[mf][kk], sAl + off);
                }
#pragma unroll
            for (int nf = 0; nf < 8; nf++) {
                uint32_t bh[4], bl[4];
                uint32_t off =
                    (uint32_t)(((wn * 64 + nf * 8 + (lid & 7)) * AST + (lid >> 3) * 8) * 2);
                ldsm4(bh, sBh + off);
                ldsm4(bl, sBl + off);
#pragma unroll
                for (int mf = 0; mf < 2; mf++)
#pragma unroll
                    for (int kk = 0; kk < 2; kk++) {
                        mma_bf(acc[mf][nf], ah[mf][kk], bh + kk * 2);
                        mma_bf(acc[mf][nf], ah[mf][kk], bl + kk * 2);
                        mma_bf(acc[mf][nf], al[mf][kk], bh + kk * 2);
                    }
            }
        }
        epi(acc);
    }
};

// =====================================================================
// Kernel 1: QKV projection (z selects W; writes split Q/K and V^T scratch)
// =====================================================================
__global__ __launch_bounds__(256, 1) void k_qkv() {
    const int tid = threadIdx.x, lid = tid & 31, w = tid >> 5;
    const int wm = w >> 1, wn = w & 1;
    const int m0 = blockIdx.x * 128, n0 = blockIdx.y * 128, z = blockIdx.z;
    const int g = lid >> 2, t = lid & 3;

    GemmBody::run(g_xhi, g_xlo, g_whi + (size_t)z * 262144, g_wlo + (size_t)z * 262144, m0, n0,
                  [&](float acc[2][8][4]) {
#pragma unroll
                      for (int mf = 0; mf < 2; mf++) {
                          int m = m0 + wm * 32 + mf * 16 + g;
                          int b = m >> 11, s = m & 2047;
#pragma unroll
                          for (int nf = 0; nf < 8; nf++) {
                              int n = n0 + wn * 64 + nf * 8 + 2 * t;
                              int h = n >> 6, d = n & 63;
                              float* cc = acc[mf][nf];
                              if (z < 2) {
                                  __nv_bfloat16* dh = (z == 0) ? g_qhi : g_khi;
                                  __nv_bfloat16* dl = (z == 0) ? g_qlo : g_klo;
                                  uint32_t h01, l01, h23, l23;
                                  splitpack(cc[0], cc[1], h01, l01);
                                  splitpack(cc[2], cc[3], h23, l23);
                                  size_t o0 = ((size_t)(b * 8 + h) * 2048 + s) * 64 + d;
                                  *(uint32_t*)(dh + o0) = h01;
                                  *(uint32_t*)(dl + o0) = l01;
                                  size_t o1 = o0 + 8 * 64;
                                  *(uint32_t*)(dh + o1) = h23;
                                  *(uint32_t*)(dl + o1) = l23;
                              } else {
                                  __nv_bfloat16 h0, l0, h1, l1, h2, l2, h3, l3;
                                  split_s(cc[0], h0, l0);
                                  split_s(cc[1], h1, l1);
                                  split_s(cc[2], h2, l2);
                                  split_s(cc[3], h3, l3);
                                  size_t o0 = ((size_t)(b * 8 + h) * 64 + d) * 2048 + s;
                                  g_vhi[o0] = h0;        g_vlo[o0] = l0;
                                  g_vhi[o0 + 2048] = h1; g_vlo[o0 + 2048] = l1;
                                  g_vhi[o0 + 8] = h2;    g_vlo[o0 + 8] = l2;
                                  g_vhi[o0 + 2056] = h3; g_vlo[o0 + 2056] = l3;
                              }
                          }
                      }
                  });
}

// =====================================================================
// Kernel 3: output projection (AO @ Wo^T -> fp32 out)
// =====================================================================
__global__ __launch_bounds__(256, 1) void k_out(float* __restrict__ out) {
    const int tid = threadIdx.x, lid = tid & 31, w = tid >> 5;
    const int wm = w >> 1, wn = w & 1;
    const int m0 = blockIdx.x * 128, n0 = blockIdx.y * 128;
    const int g = lid >> 2, t = lid & 3;

    GemmBody::run(g_ohi, g_olo, g_whi + 3u * 262144, g_wlo + 3u * 262144, m0, n0,
                  [&](float acc[2][8][4]) {
#pragma unroll
                      for (int mf = 0; mf < 2; mf++) {
                          int m = m0 + wm * 32 + mf * 16 + g;
#pragma unroll
                          for (int nf = 0; nf < 8; nf++) {
                              int n = n0 + wn * 64 + nf * 8 + 2 * t;
                              float* cc = acc[mf][nf];
                              *(float2*)(out + (size_t)m * 512 + n) = make_float2(cc[0], cc[1]);
                              *(float2*)(out + (size_t)(m + 8) * 512 + n) =
                                  make_float2(cc[2], cc[3]);
                          }
                      }
                  });
}

// =====================================================================
// Kernel 2: fused sigmoid attention, cp.async double-buffered over kv tiles.
// =====================================================================
constexpr int KST = 72;    // K-tile smem stride (elems)
constexpr int VST = 136;   // V-tile smem stride (elems)
constexpr int AS_EL = 2 * 128 * KST + 2 * 64 * VST;  // 35840 elems/stage
constexpr int ATTN_SMEM = 2 * AS_EL * 2;             // 143360 B

__global__ __launch_bounds__(256, 1) void k_attn() {
    extern __shared__ __nv_bfloat16 dsm[];
    const uint32_t u0 = smem_u32(dsm);
    const int tid = threadIdx.x, lid = tid & 31, w = tid >> 5;
    const int q0 = blockIdx.x * 128, bh = blockIdx.y;
    const int g = lid >> 2, t = lid & 3;
    const size_t qkBase = (size_t)bh * 2048 * 64;
    const size_t vBase = (size_t)bh * 131072;

    auto load_stage = [&](int j, int s) {
        uint32_t base = u0 + (uint32_t)(s * AS_EL * 2);
#pragma unroll
        for (int it = 0; it < 4; it++) {
            int ch = tid + it * 256;
            {
                int r = ch >> 3, q = ch & 7;
                size_t src = qkBase + (size_t)(j * 128 + r) * 64 + q * 8;
                uint32_t d = (uint32_t)((r * KST + q * 8) * 2);
                cp16(base + d, g_khi + src);
                cp16(base + 18432 + d, g_klo + src);
            }
            {
                int r = ch >> 4, q = ch & 15;
                size_t src = vBase + (size_t)j * 128 + (size_t)r * 2048 + q * 8;
                uint32_t d = (uint32_t)((r * VST + q * 8) * 2);
                cp16(base + 36864 + d, g_vhi + src);
                cp16(base + 54272 + d, g_vlo + src);
            }
        }
    };

    load_stage(0, 0);
    cp_commit();

    // Q fragments for this warp's 16 rows (resident whole kernel)
    uint32_t qh[4][4], ql[4][4];
    {
        const __nv_bfloat16* Qh = g_qhi + (qkBase + (size_t)(q0 + w * 16) * 64);
        const __nv_bfloat16* Ql = g_qlo + (qkBase + (size_t)(q0 + w * 16) * 64);
#pragma unroll
        for (int kk = 0; kk < 4; kk++) {
            int c0 = kk * 16 + 2 * t;
            qh[kk][0] = *(const uint32_t*)(Qh + g * 64 + c0);
            qh[kk][1] = *(const uint32_t*)(Qh + (g + 8) * 64 + c0);
            qh[kk][2] = *(const uint32_t*)(Qh + g * 64 + c0 + 8);
            qh[kk][3] = *(const uint32_t*)(Qh + (g + 8) * 64 + c0 + 8);
            ql[kk][0] = *(const uint32_t*)(Ql + g * 64 + c0);
            ql[kk][1] = *(const uint32_t*)(Ql + (g + 8) * 64 + c0);
            ql[kk][2] = *(const uint32_t*)(Ql + g * 64 + c0 + 8);
            ql[kk][3] = *(const uint32_t*)(Ql + (g + 8) * 64 + c0 + 8);
        }
    }

    float oacc[8][4];
#pragma unroll
    for (int nf = 0; nf < 8; nf++)
#pragma unroll
        for (int e = 0; e < 4; e++) oacc[nf][e] = 0.0f;

    for (int j = 0; j < 16; j++) {
        const int s = j & 1;
        __syncthreads();
        if (j < 15) {
            load_stage(j + 1, s ^ 1);
            cp_commit();
            cp_wait<1>();
        } else {
            cp_wait<0>();
        }
        __syncthreads();

        const uint32_t base = u0 + (uint32_t)(s * AS_EL * 2);
        const uint32_t uKh = base, uKl = base + 18432;
        const uint32_t uVh = base + 36864, uVl = base + 54272;

        // S = Q @ K^T (16 x 128)
        float sacc[16][4];
#pragma unroll
        for (int nf = 0; nf < 16; nf++)
#pragma unroll
            for (int e = 0; e < 4; e++) sacc[nf][e] = 0.0f;

#pragma unroll
        for (int nf = 0; nf < 16; nf++) {
            uint32_t kh[8], kl[8];
            uint32_t b0 = (uint32_t)((nf * 8 + (lid & 7)) * KST + (lid >> 3) * 8);
            ldsm4(kh, uKh + b0 * 2);
            ldsm4(kh + 4, uKh + (b0 + 32) * 2);
            ldsm4(kl, uKl + b0 * 2);
            ldsm4(kl + 4, uKl + (b0 + 32) * 2);
#pragma unroll
            for (int kk = 0; kk < 4; kk++) {
                mma_bf(sacc[nf], qh[kk], kh + 2 * kk);
                mma_bf(sacc[nf], qh[kk], kl + 2 * kk);
                mma_bf(sacc[nf], ql[kk], kh + 2 * kk);
            }
        }

        // sigmoid
#pragma unroll
        for (int nf = 0; nf < 16; nf++)
#pragma unroll
            for (int e = 0; e < 4; e++) {
                float v = sacc[nf][e] * SIG_SCALE + SIG_BIAS;
                sacc[nf][e] = __fdividef(1.0f, 1.0f + __expf(-v));
            }

        // O += P @ V
#pragma unroll
        for (int kc = 0; kc < 4; kc++) {
            uint32_t ph[2][4], pl[2][4];
#pragma unroll
            for (int u = 0; u < 2; u++) {
                float* s0 = sacc[(2 * kc + u) * 2];
                float* s1 = sacc[(2 * kc + u) * 2 + 1];
                splitpack(s0[0], s0[1], ph[u][0], pl[u][0]);
                splitpack(s0[2], s0[3], ph[u][1], pl[u][1]);
                splitpack(s1[0], s1[1], ph[u][2], pl[u][2]);
                splitpack(s1[2], s1[3], ph[u][3], pl[u][3]);
            }
#pragma unroll
            for (int nf = 0; nf < 8; nf++) {
                uint32_t vh[4], vl[4];
                uint32_t off =
                    (uint32_t)(((nf * 8 + (lid & 7)) * VST + kc * 32 + (lid >> 3) * 8) * 2);
                ldsm4(vh, uVh + off);
                ldsm4(vl, uVl + off);
#pragma unroll
                for (int u = 0; u < 2; u++) {
                    mma_bf(oacc[nf], ph[u], vh + 2 * u);
                    mma_bf(oacc[nf], ph[u], vl + 2 * u);
                    mma_bf(oacc[nf], pl[u], vh + 2 * u);
                }
            }
        }
    }

    // epilogue: split O -> AO scratch [8192, 512]
    {
        const int b = bh >> 3, h = bh & 7;
        const int s = q0 + w * 16 + g;
#pragma unroll
        for (int nf = 0; nf < 8; nf++) {
            int d = nf * 8 + 2 * t;
            uint32_t h01, l01, h23, l23;
            splitpack(oacc[nf][0], oacc[nf][1], h01, l01);
            splitpack(oacc[nf][2], oacc[nf][3], h23, l23);
            size_t o0 = ((size_t)b * 2048 + s) * 512 + h * 64 + d;
            *(uint32_t*)(g_ohi + o0) = h01;
            *(uint32_t*)(g_olo + o0) = l01;
            size_t o1 = o0 + 8 * 512;
            *(uint32_t*)(g_ohi + o1) = h23;
            *(uint32_t*)(g_olo + o1) = l23;
        }
    }
}

// =====================================================================
extern "C" void kernel_launch(void* const* d_in, const int* in_sizes, int n_in,
                              void* d_out, int out_size) {
    const float* x = (const float*)d_in[0];
    const float* Wq = (const float*)d_in[1];
    const float* Wk = (const float*)d_in[2];
    const float* Wv = (const float*)d_in[3];
    const float* Wo = (const float*)d_in[4];
    float* out = (float*)d_out;

    cudaFuncSetAttribute(k_qkv, cudaFuncAttributeMaxDynamicSharedMemorySize, GEMM_SMEM);
    cudaFuncSetAttribute(k_out, cudaFuncAttributeMaxDynamicSharedMemorySize, GEMM_SMEM);
    cudaFuncSetAttribute(k_attn, cudaFuncAttributeMaxDynamicSharedMemorySize, ATTN_SMEM);

    k_split<<<5120, 256>>>(x, Wq, Wk, Wv, Wo);
    k_qkv<<<dim3(64, 4, 3), 256, GEMM_SMEM>>>();
    k_attn<<<dim3(16, 32), 256, ATTN_SMEM>>>();
    k_out<<<dim3(64, 4), 256, GEMM_SMEM>>>(out);
}

// round 5
// speedup vs baseline: 1.6577x; 1.6577x over previous
#include <cuda_runtime.h>
#include <cuda_bf16.h>
#include <cuda_fp16.h>
#include <stdint.h>

#define DI __device__ __forceinline__

// ---------------- scratch (static device globals; no allocation) ----------------
#define SCR_ELEMS (4u * 8u * 2048u * 64u)  // 4,194,304
__device__ __align__(16) __nv_bfloat16 g_qhi[SCR_ELEMS];
__device__ __align__(16) __nv_bfloat16 g_qlo[SCR_ELEMS];
__device__ __align__(16) __nv_bfloat16 g_khi[SCR_ELEMS];
__device__ __align__(16) __nv_bfloat16 g_klo[SCR_ELEMS];
__device__ __align__(16) __half       g_vh [SCR_ELEMS];  // V^T fp16: [B,H,D,S]
__device__ __align__(16) __nv_bfloat16 g_ohi[SCR_ELEMS]; // AO: [8192, 512]
__device__ __align__(16) __nv_bfloat16 g_olo[SCR_ELEMS];

// ---------------- helpers ----------------
DI uint32_t smem_u32(const void* p) {
    uint32_t a;
    asm("{ .reg .u64 t; cvta.to.shared.u64 t, %1; cvt.u32.u64 %0, t; }" : "=r"(a) : "l"(p));
    return a;
}
DI void ldsm4(uint32_t* r, uint32_t a) {
    asm volatile("ldmatrix.sync.aligned.m8n8.x4.shared.b16 {%0,%1,%2,%3}, [%4];"
                 : "=r"(r[0]), "=r"(r[1]), "=r"(r[2]), "=r"(r[3]) : "r"(a));
}
DI void mma_bf(float* c, const uint32_t* a, const uint32_t* b) {
    asm volatile(
        "mma.sync.aligned.m16n8k16.row.col.f32.bf16.bf16.f32 "
        "{%0,%1,%2,%3}, {%4,%5,%6,%7}, {%8,%9}, {%0,%1,%2,%3};"
        : "+f"(c[0]), "+f"(c[1]), "+f"(c[2]), "+f"(c[3])
        : "r"(a[0]), "r"(a[1]), "r"(a[2]), "r"(a[3]), "r"(b[0]), "r"(b[1]));
}
DI void mma_f16(float* c, const uint32_t* a, const uint32_t* b) {
    asm volatile(
        "mma.sync.aligned.m16n8k16.row.col.f32.f16.f16.f32 "
        "{%0,%1,%2,%3}, {%4,%5,%6,%7}, {%8,%9}, {%0,%1,%2,%3};"
        : "+f"(c[0]), "+f"(c[1]), "+f"(c[2]), "+f"(c[3])
        : "r"(a[0]), "r"(a[1]), "r"(a[2]), "r"(a[3]), "r"(b[0]), "r"(b[1]));
}
DI void split_s(float f, __nv_bfloat16& h, __nv_bfloat16& l) {
    h = __float2bfloat16_rn(f);
    l = __float2bfloat16_rn(f - __bfloat162float(h));
}
DI void splitpack(float f0, float f1, uint32_t& ph, uint32_t& pl) {
    __nv_bfloat162 vh, vl;
    vh.x = __float2bfloat16_rn(f0);
    vh.y = __float2bfloat16_rn(f1);
    vl.x = __float2bfloat16_rn(f0 - __bfloat162float(vh.x));
    vl.y = __float2bfloat16_rn(f1 - __bfloat162float(vh.y));
    ph = *reinterpret_cast<uint32_t*>(&vh);
    pl = *reinterpret_cast<uint32_t*>(&vl);
}
// sigmoid(qk/8 - log 2048) = 1 / (1 + 2^(11 - qk*0.125*log2(e)))
DI float sigmoid_fast(float qk) {
    float t = fmaf(qk, -0.18033688011112042f, 11.0f);
    float z;
    asm("ex2.approx.f32 %0, %1;" : "=f"(z) : "f"(t));
    float r;
    asm("rcp.approx.f32 %0, %1;" : "=f"(r) : "f"(1.0f + z));
    return r;
}
DI uint32_t packh2(float a, float b) {
    __half2 h = __floats2half2_rn(a, b);
    return *reinterpret_cast<uint32_t*>(&h);
}

constexpr int AST = 40;  // padded smem row stride (elems)

// =====================================================================
// Kernel 1: QKV projection. C[8192,512] = x @ W^T  (z selects W).
// BM=128 BN=128 BK=32, 256 thr, register-prefetched LDG, split-bf16 3-combo.
// =====================================================================
__global__ __launch_bounds__(256, 1) void k_qkv(const float* __restrict__ x,
                                                const float* __restrict__ Wq,
                                                const float* __restrict__ Wk,
                                                const float* __restrict__ Wv) {
    __shared__ __nv_bfloat16 sAh[128 * AST], sAl[128 * AST];
    __shared__ __nv_bfloat16 sBh[128 * AST], sBl[128 * AST];
    const int tid = threadIdx.x, lid = tid & 31, w = tid >> 5;
    const int wm = w >> 1, wn = w & 1;
    const int m0 = blockIdx.x * 128, n0 = blockIdx.y * 128, z = blockIdx.z;
    const float* __restrict__ W = (z == 0) ? Wq : ((z == 1) ? Wk : Wv);
    const uint32_t uAh = smem_u32(sAh), uAl = smem_u32(sAl);
    const uint32_t uBh = smem_u32(sBh), uBl = smem_u32(sBl);
    const int g = lid >> 2, t = lid & 3;

    float acc[2][8][4];
#pragma unroll
    for (int mf = 0; mf < 2; mf++)
#pragma unroll
        for (int nf = 0; nf < 8; nf++)
#pragma unroll
            for (int e = 0; e < 4; e++) acc[mf][nf][e] = 0.0f;

    float4 nA[4], nB[4];
    {
        const int r = tid >> 3, q = tid & 7;  // same for all it via +32 rows
#pragma unroll
        for (int it = 0; it < 4; it++) {
            nA[it] = ((const float4*)x)[(size_t)(m0 + r + it * 32) * 128 + q];
            nB[it] = ((const float4*)W)[(size_t)(n0 + r + it * 32) * 128 + q];
        }
    }

    for (int c = 0; c < 16; c++) {
        __syncthreads();
        {
            const int r = tid >> 3, q = tid & 7;
#pragma unroll
            for (int it = 0; it < 4; it++) {
                uint32_t h0, l0, h1, l1;
                splitpack(nA[it].x, nA[it].y, h0, l0);
                splitpack(nA[it].z, nA[it].w, h1, l1);
                *(uint2*)(sAh + (r + it * 32) * AST + q * 4) = make_uint2(h0, h1);
                *(uint2*)(sAl + (r + it * 32) * AST + q * 4) = make_uint2(l0, l1);
                splitpack(nB[it].x, nB[it].y, h0, l0);
                splitpack(nB[it].z, nB[it].w, h1, l1);
                *(uint2*)(sBh + (r + it * 32) * AST + q * 4) = make_uint2(h0, h1);
                *(uint2*)(sBl + (r + it * 32) * AST + q * 4) = make_uint2(l0, l1);
            }
        }
        __syncthreads();
        if (c < 15) {  // prefetch next chunk into regs; latency hides behind MMA
            const int r = tid >> 3, q = tid & 7;
#pragma unroll
            for (int it = 0; it < 4; it++) {
                nA[it] = ((const float4*)x)[(size_t)(m0 + r + it * 32) * 128 + (c + 1) * 8 + q];
                nB[it] = ((const float4*)W)[(size_t)(n0 + r + it * 32) * 128 + (c + 1) * 8 + q];
            }
        }

        uint32_t ah[2][2][4], al[2][2][4];
#pragma unroll
        for (int mf = 0; mf < 2; mf++)
#pragma unroll
            for (int kk = 0; kk < 2; kk++) {
                uint32_t off = (uint32_t)(((wm * 32 + mf * 16 + (lid & 15)) * AST +
                                           kk * 16 + (lid >> 4) * 8) * 2);
                ldsm4(ah[mf][kk], uAh + off);
                ldsm4(al[mf][kk], uAl + off);
            }
#pragma unroll
        for (int nfp = 0; nfp < 4; nfp++) {
            const int nf0 = 2 * nfp, nf1 = nf0 + 1;
            uint32_t bh0[4], bl0[4], bh1[4], bl1[4];
            uint32_t o0 = (uint32_t)(((wn * 64 + nf0 * 8 + (lid & 7)) * AST + (lid >> 3) * 8) * 2);
            uint32_t o1 = (uint32_t)(((wn * 64 + nf1 * 8 + (lid & 7)) * AST + (lid >> 3) * 8) * 2);
            ldsm4(bh0, uBh + o0);
            ldsm4(bl0, uBl + o0);
            ldsm4(bh1, uBh + o1);
            ldsm4(bl1, uBl + o1);
#pragma unroll
            for (int mf = 0; mf < 2; mf++)
#pragma unroll
                for (int kk = 0; kk < 2; kk++) {
                    mma_bf(acc[mf][nf0], ah[mf][kk], bh0 + kk * 2);
                    mma_bf(acc[mf][nf1], ah[mf][kk], bh1 + kk * 2);
                    mma_bf(acc[mf][nf0], ah[mf][kk], bl0 + kk * 2);
                    mma_bf(acc[mf][nf1], ah[mf][kk], bl1 + kk * 2);
                    mma_bf(acc[mf][nf0], al[mf][kk], bh0 + kk * 2);
                    mma_bf(acc[mf][nf1], al[mf][kk], bh1 + kk * 2);
                }
        }
    }

    // epilogue: split to scratch (Q/K bf16-split; V fp16 transposed)
#pragma unroll
    for (int mf = 0; mf < 2; mf++) {
        int m = m0 + wm * 32 + mf * 16 + g;
        int b = m >> 11, s = m & 2047;
#pragma unroll
        for (int nf = 0; nf < 8; nf++) {
            int n = n0 + wn * 64 + nf * 8 + 2 * t;
            int h = n >> 6, d = n & 63;
            float* cc = acc[mf][nf];
            if (z < 2) {
                __nv_bfloat16* dh = (z == 0) ? g_qhi : g_khi;
                __nv_bfloat16* dl = (z == 0) ? g_qlo : g_klo;
                uint32_t h01, l01, h23, l23;
                splitpack(cc[0], cc[1], h01, l01);
                splitpack(cc[2], cc[3], h23, l23);
                size_t o0 = ((size_t)(b * 8 + h) * 2048 + s) * 64 + d;
                *(uint32_t*)(dh + o0) = h01;
                *(uint32_t*)(dl + o0) = l01;
                size_t o1 = o0 + 8 * 64;
                *(uint32_t*)(dh + o1) = h23;
                *(uint32_t*)(dl + o1) = l23;
            } else {
                size_t o0 = ((size_t)(b * 8 + h) * 64 + d) * 2048 + s;
                g_vh[o0] = __float2half_rn(cc[0]);
                g_vh[o0 + 2048] = __float2half_rn(cc[1]);
                g_vh[o0 + 8] = __float2half_rn(cc[2]);
                g_vh[o0 + 2056] = __float2half_rn(cc[3]);
            }
        }
    }
}

// =====================================================================
// Kernel 2: fused sigmoid attention. QK split-bf16 3-combo; PV fp16 1-combo.
// =====================================================================
constexpr int KST = 72;   // K-tile smem stride (elems)
constexpr int VST = 136;  // V-tile smem stride (elems)
constexpr int ATTN_SMEM = 2 * 128 * KST * 2 + 64 * VST * 2;  // 54272 B

__global__ __launch_bounds__(256, 1) void k_attn() {
    extern __shared__ __nv_bfloat16 dsm[];
    __nv_bfloat16* sKh = dsm;
    __nv_bfloat16* sKl = dsm + 128 * KST;
    __half* sV = (__half*)(dsm + 2 * 128 * KST);
    const uint32_t uKh = smem_u32(sKh), uKl = smem_u32(sKl), uV = smem_u32(sV);

    const int tid = threadIdx.x, lid = tid & 31, w = tid >> 5;
    const int q0 = blockIdx.x * 128, bh = blockIdx.y;
    const int g = lid >> 2, t = lid & 3;
    const size_t qkBase = (size_t)bh * 2048 * 64;
    const size_t vBase = (size_t)bh * 131072;

    // Q fragments for this warp's 16 rows (resident whole kernel)
    uint32_t qh[4][4], ql[4][4];
    {
        const __nv_bfloat16* Qh = g_qhi + qkBase + (size_t)(q0 + w * 16) * 64;
        const __nv_bfloat16* Ql = g_qlo + qkBase + (size_t)(q0 + w * 16) * 64;
#pragma unroll
        for (int kk = 0; kk < 4; kk++) {
            int c0 = kk * 16 + 2 * t;
            qh[kk][0] = *(const uint32_t*)(Qh + g * 64 + c0);
            qh[kk][1] = *(const uint32_t*)(Qh + (g + 8) * 64 + c0);
            qh[kk][2] = *(const uint32_t*)(Qh + g * 64 + c0 + 8);
            qh[kk][3] = *(const uint32_t*)(Qh + (g + 8) * 64 + c0 + 8);
            ql[kk][0] = *(const uint32_t*)(Ql + g * 64 + c0);
            ql[kk][1] = *(const uint32_t*)(Ql + (g + 8) * 64 + c0);
            ql[kk][2] = *(const uint32_t*)(Ql + g * 64 + c0 + 8);
            ql[kk][3] = *(const uint32_t*)(Ql + (g + 8) * 64 + c0 + 8);
        }
    }

    float oacc[8][4];
#pragma unroll
    for (int nf = 0; nf < 8; nf++)
#pragma unroll
        for (int e = 0; e < 4; e++) oacc[nf][e] = 0.0f;

    for (int j = 0; j < 16; j++) {
        __syncthreads();
        {
            const float4* Kh = (const float4*)(g_khi + qkBase + (size_t)j * 128 * 64);
            const float4* Kl = (const float4*)(g_klo + qkBase + (size_t)j * 128 * 64);
#pragma unroll
            for (int it = 0; it < 4; it++) {
                int i = tid + it * 256, r = i >> 3, q = i & 7;
                *(float4*)(sKh + r * KST + q * 8) = Kh[r * 8 + q];
                *(float4*)(sKl + r * KST + q * 8) = Kl[r * 8 + q];
            }
            const float4* V = (const float4*)(g_vh + vBase + (size_t)j * 128);
#pragma unroll
            for (int it = 0; it < 4; it++) {
                int i = tid + it * 256, r = i >> 4, q = i & 15;
                *(float4*)(sV + r * VST + q * 8) = V[r * 256 + q];
            }
        }
        __syncthreads();

        // S = Q @ K^T (16 x 128), nf-pair interleaved accumulator chains
        float sacc[16][4];
#pragma unroll
        for (int nf = 0; nf < 16; nf++)
#pragma unroll
            for (int e = 0; e < 4; e++) sacc[nf][e] = 0.0f;

#pragma unroll
        for (int nfp = 0; nfp < 8; nfp++) {
            const int nf0 = 2 * nfp, nf1 = nf0 + 1;
            uint32_t kh0[8], kl0[8], kh1[8], kl1[8];
            uint32_t b0 = (uint32_t)((nf0 * 8 + (lid & 7)) * KST + (lid >> 3) * 8);
            uint32_t b1 = (uint32_t)((nf1 * 8 + (lid & 7)) * KST + (lid >> 3) * 8);
            ldsm4(kh0, uKh + b0 * 2);
            ldsm4(kh0 + 4, uKh + (b0 + 32) * 2);
            ldsm4(kl0, uKl + b0 * 2);
            ldsm4(kl0 + 4, uKl + (b0 + 32) * 2);
            ldsm4(kh1, uKh + b1 * 2);
            ldsm4(kh1 + 4, uKh + (b1 + 32) * 2);
            ldsm4(kl1, uKl + b1 * 2);
            ldsm4(kl1 + 4, uKl + (b1 + 32) * 2);
#pragma unroll
            for (int kk = 0; kk < 4; kk++) {
                mma_bf(sacc[nf0], qh[kk], kh0 + 2 * kk);
                mma_bf(sacc[nf1], qh[kk], kh1 + 2 * kk);
                mma_bf(sacc[nf0], qh[kk], kl0 + 2 * kk);
                mma_bf(sacc[nf1], qh[kk], kl1 + 2 * kk);
                mma_bf(sacc[nf0], ql[kk], kh0 + 2 * kk);
                mma_bf(sacc[nf1], ql[kk], kh1 + 2 * kk);
            }
        }

        // sigmoid (2-MUFU fast path)
#pragma unroll
        for (int nf = 0; nf < 16; nf++)
#pragma unroll
            for (int e = 0; e < 4; e++) sacc[nf][e] = sigmoid_fast(sacc[nf][e]);

        // O += P @ V, fp16 single-combo
#pragma unroll
        for (int kc = 0; kc < 4; kc++) {
            uint32_t ph[2][4];
#pragma unroll
            for (int u = 0; u < 2; u++) {
                float* s0 = sacc[4 * kc + 2 * u];
                float* s1 = sacc[4 * kc + 2 * u + 1];
                ph[u][0] = packh2(s0[0], s0[1]);
                ph[u][1] = packh2(s0[2], s0[3]);
                ph[u][2] = packh2(s1[0], s1[1]);
                ph[u][3] = packh2(s1[2], s1[3]);
            }
#pragma unroll
            for (int nfp = 0; nfp < 4; nfp++) {
                const int nf0 = 2 * nfp, nf1 = nf0 + 1;
                uint32_t vh0[4], vh1[4];
                uint32_t o0 =
                    (uint32_t)(((nf0 * 8 + (lid & 7)) * VST + kc * 32 + (lid >> 3) * 8) * 2);
                uint32_t o1 =
                    (uint32_t)(((nf1 * 8 + (lid & 7)) * VST + kc * 32 + (lid >> 3) * 8) * 2);
                ldsm4(vh0, uV + o0);
                ldsm4(vh1, uV + o1);
#pragma unroll
                for (int u = 0; u < 2; u++) {
                    mma_f16(oacc[nf0], ph[u], vh0 + 2 * u);
                    mma_f16(oacc[nf1], ph[u], vh1 + 2 * u);
                }
            }
        }
    }

    // epilogue: split O -> AO scratch [8192, 512]
    {
        const int b = bh >> 3, h = bh & 7;
        const int s = q0 + w * 16 + g;
#pragma unroll
        for (int nf = 0; nf < 8; nf++) {
            int d = nf * 8 + 2 * t;
            uint32_t h01, l01, h23, l23;
            splitpack(oacc[nf][0], oacc[nf][1], h01, l01);
            splitpack(oacc[nf][2], oacc[nf][3], h23, l23);
            size_t o0 = ((size_t)b * 2048 + s) * 512 + h * 64 + d;
            *(uint32_t*)(g_ohi + o0) = h01;
            *(uint32_t*)(g_olo + o0) = l01;
            size_t o1 = o0 + 8 * 512;
            *(uint32_t*)(g_ohi + o1) = h23;
            *(uint32_t*)(g_olo + o1) = l23;
        }
    }
}

// =====================================================================
// Kernel 3: output projection. out[8192,512] = AO @ Wo^T (fp32 out)
// =====================================================================
__global__ __launch_bounds__(256, 1) void k_out(const float* __restrict__ Wo,
                                                float* __restrict__ out) {
    __shared__ __nv_bfloat16 sAh[128 * AST], sAl[128 * AST];
    __shared__ __nv_bfloat16 sBh[128 * AST], sBl[128 * AST];
    const int tid = threadIdx.x, lid = tid & 31, w = tid >> 5;
    const int wm = w >> 1, wn = w & 1;
    const int m0 = blockIdx.x * 128, n0 = blockIdx.y * 128;
    const uint32_t uAh = smem_u32(sAh), uAl = smem_u32(sAl);
    const uint32_t uBh = smem_u32(sBh), uBl = smem_u32(sBl);
    const int g = lid >> 2, t = lid & 3;

    float acc[2][8][4];
#pragma unroll
    for (int mf = 0; mf < 2; mf++)
#pragma unroll
        for (int nf = 0; nf < 8; nf++)
#pragma unroll
            for (int e = 0; e < 4; e++) acc[mf][nf][e] = 0.0f;

    float4 nAh[2], nAl[2], nB[4];
    {
        const int rA = tid >> 2, qA = tid & 3;
        const int rB = tid >> 3, qB = tid & 7;
#pragma unroll
        for (int it = 0; it < 2; it++) {
            size_t src = (size_t)(m0 + rA + it * 64) * 64 + qA;
            nAh[it] = ((const float4*)g_ohi)[src];
            nAl[it] = ((const float4*)g_olo)[src];
        }
#pragma unroll
        for (int it = 0; it < 4; it++)
            nB[it] = ((const float4*)Wo)[(size_t)(n0 + rB + it * 32) * 128 + qB];
    }

    for (int c = 0; c < 16; c++) {
        __syncthreads();
        {
            const int rA = tid >> 2, qA = tid & 3;
            const int rB = tid >> 3, qB = tid & 7;
#pragma unroll
            for (int it = 0; it < 2; it++) {
                *(float4*)(sAh + (rA + it * 64) * AST + qA * 8) = nAh[it];
                *(float4*)(sAl + (rA + it * 64) * AST + qA * 8) = nAl[it];
            }
#pragma unroll
            for (int it = 0; it < 4; it++) {
                uint32_t h0, l0, h1, l1;
                splitpack(nB[it].x, nB[it].y, h0, l0);
                splitpack(nB[it].z, nB[it].w, h1, l1);
                *(uint2*)(sBh + (rB + it * 32) * AST + qB * 4) = make_uint2(h0, h1);
                *(uint2*)(sBl + (rB + it * 32) * AST + qB * 4) = make_uint2(l0, l1);
            }
        }
        __syncthreads();
        if (c < 15) {
            const int rA = tid >> 2, qA = tid & 3;
            const int rB = tid >> 3, qB = tid & 7;
#pragma unroll
            for (int it = 0; it < 2; it++) {
                size_t src = (size_t)(m0 + rA + it * 64) * 64 + (c + 1) * 4 + qA;
                nAh[it] = ((const float4*)g_ohi)[src];
                nAl[it] = ((const float4*)g_olo)[src];
            }
#pragma unroll
            for (int it = 0; it < 4; it++)
                nB[it] = ((const float4*)Wo)[(size_t)(n0 + rB + it * 32) * 128 + (c + 1) * 8 + qB];
        }

        uint32_t ah[2][2][4], al[2][2][4];
#pragma unroll
        for (int mf = 0; mf < 2; mf++)
#pragma unroll
            for (int kk = 0; kk < 2; kk++) {
                uint32_t off = (uint32_t)(((wm * 32 + mf * 16 + (lid & 15)) * AST +
                                           kk * 16 + (lid >> 4) * 8) * 2);
                ldsm4(ah[mf][kk], uAh + off);
                ldsm4(al[mf][kk], uAl + off);
            }
#pragma unroll
        for (int nfp = 0; nfp < 4; nfp++) {
            const int nf0 = 2 * nfp, nf1 = nf0 + 1;
            uint32_t bh0[4], bl0[4], bh1[4], bl1[4];
            uint32_t o0 = (uint32_t)(((wn * 64 + nf0 * 8 + (lid & 7)) * AST + (lid >> 3) * 8) * 2);
            uint32_t o1 = (uint32_t)(((wn * 64 + nf1 * 8 + (lid & 7)) * AST + (lid >> 3) * 8) * 2);
            ldsm4(bh0, uBh + o0);
            ldsm4(bl0, uBl + o0);
            ldsm4(bh1, uBh + o1);
            ldsm4(bl1, uBl + o1);
#pragma unroll
            for (int mf = 0; mf < 2; mf++)
#pragma unroll
                for (int kk = 0; kk < 2; kk++) {
                    mma_bf(acc[mf][nf0], ah[mf][kk], bh0 + kk * 2);
                    mma_bf(acc[mf][nf1], ah[mf][kk], bh1 + kk * 2);
                    mma_bf(acc[mf][nf0], ah[mf][kk], bl0 + kk * 2);
                    mma_bf(acc[mf][nf1], ah[mf][kk], bl1 + kk * 2);
                    mma_bf(acc[mf][nf0], al[mf][kk], bh0 + kk * 2);
                    mma_bf(acc[mf][nf1], al[mf][kk], bh1 + kk * 2);
                }
        }
    }

    // epilogue: fp32 direct to output
#pragma unroll
    for (int mf = 0; mf < 2; mf++) {
        int m = m0 + wm * 32 + mf * 16 + g;
#pragma unroll
        for (int nf = 0; nf < 8; nf++) {
            int n = n0 + wn * 64 + nf * 8 + 2 * t;
            float* cc = acc[mf][nf];
            *(float2*)(out + (size_t)m * 512 + n) = make_float2(cc[0], cc[1]);
            *(float2*)(out + (size_t)(m + 8) * 512 + n) = make_float2(cc[2], cc[3]);
        }
    }
}

// =====================================================================
extern "C" void kernel_launch(void* const* d_in, const int* in_sizes, int n_in,
                              void* d_out, int out_size) {
    const float* x = (const float*)d_in[0];
    const float* Wq = (const float*)d_in[1];
    const float* Wk = (const float*)d_in[2];
    const float* Wv = (const float*)d_in[3];
    const float* Wo = (const float*)d_in[4];
    float* out = (float*)d_out;

    cudaFuncSetAttribute(k_attn, cudaFuncAttributeMaxDynamicSharedMemorySize, ATTN_SMEM);

    k_qkv<<<dim3(64, 4, 3), 256>>>(x, Wq, Wk, Wv);
    k_attn<<<dim3(16, 32), 256, ATTN_SMEM>>>();
    k_out<<<dim3(64, 4), 256>>>(Wo, out);
}

// round 6
// speedup vs baseline: 1.8444x; 1.1126x over previous
#include <cuda_runtime.h>
#include <cuda_bf16.h>
#include <cuda_fp16.h>
#include <stdint.h>

#define DI __device__ __forceinline__

// ---------------- scratch (static device globals; no allocation) ----------------
#define SCR_ELEMS (4u * 8u * 2048u * 64u)  // 4,194,304
__device__ __align__(16) __nv_bfloat16 g_qhi[SCR_ELEMS];
__device__ __align__(16) __nv_bfloat16 g_qlo[SCR_ELEMS];
__device__ __align__(16) __nv_bfloat16 g_khi[SCR_ELEMS];
__device__ __align__(16) __nv_bfloat16 g_klo[SCR_ELEMS];
__device__ __align__(16) __half       g_vh [SCR_ELEMS];  // V^T fp16: [B,H,D,S]
__device__ __align__(16) __nv_bfloat16 g_ohi[SCR_ELEMS]; // AO: [8192, 512]
__device__ __align__(16) __nv_bfloat16 g_olo[SCR_ELEMS];

// ---------------- helpers ----------------
DI uint32_t smem_u32(const void* p) {
    uint32_t a;
    asm("{ .reg .u64 t; cvta.to.shared.u64 t, %1; cvt.u32.u64 %0, t; }" : "=r"(a) : "l"(p));
    return a;
}
DI void ldsm4(uint32_t* r, uint32_t a) {
    asm volatile("ldmatrix.sync.aligned.m8n8.x4.shared.b16 {%0,%1,%2,%3}, [%4];"
                 : "=r"(r[0]), "=r"(r[1]), "=r"(r[2]), "=r"(r[3]) : "r"(a));
}
DI void mma_bf(float* c, const uint32_t* a, const uint32_t* b) {
    asm volatile(
        "mma.sync.aligned.m16n8k16.row.col.f32.bf16.bf16.f32 "
        "{%0,%1,%2,%3}, {%4,%5,%6,%7}, {%8,%9}, {%0,%1,%2,%3};"
        : "+f"(c[0]), "+f"(c[1]), "+f"(c[2]), "+f"(c[3])
        : "r"(a[0]), "r"(a[1]), "r"(a[2]), "r"(a[3]), "r"(b[0]), "r"(b[1]));
}
DI void mma_f16(float* c, const uint32_t* a, const uint32_t* b) {
    asm volatile(
        "mma.sync.aligned.m16n8k16.row.col.f32.f16.f16.f32 "
        "{%0,%1,%2,%3}, {%4,%5,%6,%7}, {%8,%9}, {%0,%1,%2,%3};"
        : "+f"(c[0]), "+f"(c[1]), "+f"(c[2]), "+f"(c[3])
        : "r"(a[0]), "r"(a[1]), "r"(a[2]), "r"(a[3]), "r"(b[0]), "r"(b[1]));
}
DI void splitpack(float f0, float f1, uint32_t& ph, uint32_t& pl) {
    __nv_bfloat162 vh, vl;
    vh.x = __float2bfloat16_rn(f0);
    vh.y = __float2bfloat16_rn(f1);
    vl.x = __float2bfloat16_rn(f0 - __bfloat162float(vh.x));
    vl.y = __float2bfloat16_rn(f1 - __bfloat162float(vh.y));
    ph = *reinterpret_cast<uint32_t*>(&vh);
    pl = *reinterpret_cast<uint32_t*>(&vl);
}
// sigmoid(qk/8 - log 2048) = 1 / (1 + 2^(11 - qk*0.125*log2(e)))
DI float sigmoid_fast(float qk) {
    float t = fmaf(qk, -0.18033688011112042f, 11.0f);
    float z;
    asm("ex2.approx.f32 %0, %1;" : "=f"(z) : "f"(t));
    float r;
    asm("rcp.approx.f32 %0, %1;" : "=f"(r) : "f"(1.0f + z));
    return r;
}
DI uint32_t packh2(float a, float b) {
    __half2 h = __floats2half2_rn(a, b);
    return *reinterpret_cast<uint32_t*>(&h);
}

constexpr int AST = 40;  // padded smem row stride (elems)

// =====================================================================
// Kernel 1: QKV projection. C[8192,512] = x @ W^T  (z selects W).
// BM=128 BN=128 BK=32, 512 thr (16 warps 4m x 4n), split-bf16 3-combo.
// =====================================================================
__global__ __launch_bounds__(512, 1) void k_qkv(const float* __restrict__ x,
                                                const float* __restrict__ Wq,
                                                const float* __restrict__ Wk,
                                                const float* __restrict__ Wv) {
    __shared__ __nv_bfloat16 sAh[128 * AST], sAl[128 * AST];
    __shared__ __nv_bfloat16 sBh[128 * AST], sBl[128 * AST];
    const int tid = threadIdx.x, lid = tid & 31, w = tid >> 5;
    const int wm = w >> 2, wn = w & 3;
    const int m0 = blockIdx.x * 128, n0 = blockIdx.y * 128, z = blockIdx.z;
    const float* __restrict__ W = (z == 0) ? Wq : ((z == 1) ? Wk : Wv);
    const uint32_t uAh = smem_u32(sAh), uAl = smem_u32(sAl);
    const uint32_t uBh = smem_u32(sBh), uBl = smem_u32(sBl);
    const int g = lid >> 2, t = lid & 3;

    float acc[2][4][4];
#pragma unroll
    for (int mf = 0; mf < 2; mf++)
#pragma unroll
        for (int nf = 0; nf < 4; nf++)
#pragma unroll
            for (int e = 0; e < 4; e++) acc[mf][nf][e] = 0.0f;

    for (int c = 0; c < 16; c++) {
        __syncthreads();
        {
            const int r = tid >> 3, q = tid & 7;  // 64 rows per it, 2 its
#pragma unroll
            for (int it = 0; it < 2; it++) {
                float4 fA = ((const float4*)x)[(size_t)(m0 + r + it * 64) * 128 + c * 8 + q];
                float4 fB = ((const float4*)W)[(size_t)(n0 + r + it * 64) * 128 + c * 8 + q];
                uint32_t h0, l0, h1, l1;
                splitpack(fA.x, fA.y, h0, l0);
                splitpack(fA.z, fA.w, h1, l1);
                *(uint2*)(sAh + (r + it * 64) * AST + q * 4) = make_uint2(h0, h1);
                *(uint2*)(sAl + (r + it * 64) * AST + q * 4) = make_uint2(l0, l1);
                splitpack(fB.x, fB.y, h0, l0);
                splitpack(fB.z, fB.w, h1, l1);
                *(uint2*)(sBh + (r + it * 64) * AST + q * 4) = make_uint2(h0, h1);
                *(uint2*)(sBl + (r + it * 64) * AST + q * 4) = make_uint2(l0, l1);
            }
        }
        __syncthreads();

        uint32_t ah[2][2][4], al[2][2][4];
#pragma unroll
        for (int mf = 0; mf < 2; mf++)
#pragma unroll
            for (int kk = 0; kk < 2; kk++) {
                uint32_t off = (uint32_t)(((wm * 32 + mf * 16 + (lid & 15)) * AST +
                                           kk * 16 + (lid >> 4) * 8) * 2);
                ldsm4(ah[mf][kk], uAh + off);
                ldsm4(al[mf][kk], uAl + off);
            }
#pragma unroll
        for (int nf = 0; nf < 4; nf++) {
            uint32_t bh[4], bl[4];
            uint32_t off =
                (uint32_t)(((wn * 32 + nf * 8 + (lid & 7)) * AST + (lid >> 3) * 8) * 2);
            ldsm4(bh, uBh + off);
            ldsm4(bl, uBl + off);
#pragma unroll
            for (int mf = 0; mf < 2; mf++)
#pragma unroll
                for (int kk = 0; kk < 2; kk++) {
                    mma_bf(acc[mf][nf], ah[mf][kk], bh + kk * 2);
                    mma_bf(acc[mf][nf], ah[mf][kk], bl + kk * 2);
                    mma_bf(acc[mf][nf], al[mf][kk], bh + kk * 2);
                }
        }
    }

    // epilogue: split to scratch (Q/K bf16-split; V fp16 transposed)
#pragma unroll
    for (int mf = 0; mf < 2; mf++) {
        int m = m0 + wm * 32 + mf * 16 + g;
        int b = m >> 11, s = m & 2047;
#pragma unroll
        for (int nf = 0; nf < 4; nf++) {
            int n = n0 + wn * 32 + nf * 8 + 2 * t;
            int h = n >> 6, d = n & 63;
            float* cc = acc[mf][nf];
            if (z < 2) {
                __nv_bfloat16* dh = (z == 0) ? g_qhi : g_khi;
                __nv_bfloat16* dl = (z == 0) ? g_qlo : g_klo;
                uint32_t h01, l01, h23, l23;
                splitpack(cc[0], cc[1], h01, l01);
                splitpack(cc[2], cc[3], h23, l23);
                size_t o0 = ((size_t)(b * 8 + h) * 2048 + s) * 64 + d;
                *(uint32_t*)(dh + o0) = h01;
                *(uint32_t*)(dl + o0) = l01;
                size_t o1 = o0 + 8 * 64;
                *(uint32_t*)(dh + o1) = h23;
                *(uint32_t*)(dl + o1) = l23;
            } else {
                size_t o0 = ((size_t)(b * 8 + h) * 64 + d) * 2048 + s;
                g_vh[o0] = __float2half_rn(cc[0]);
                g_vh[o0 + 2048] = __float2half_rn(cc[1]);
                g_vh[o0 + 8] = __float2half_rn(cc[2]);
                g_vh[o0 + 2056] = __float2half_rn(cc[3]);
            }
        }
    }
}

// =====================================================================
// Kernel 2: fused sigmoid attention. 512 thr, q-tile 256 rows (16 warps
// x 16 rows). S computed in 4 chunks of 32 cols (register-lean), PV fp16.
// =====================================================================
constexpr int KST = 72;   // K-tile smem stride (elems)
constexpr int VST = 136;  // V-tile smem stride (elems)
constexpr int ATTN_SMEM = 2 * 128 * KST * 2 + 64 * VST * 2;  // 54272 B

__global__ __launch_bounds__(512, 1) void k_attn() {
    extern __shared__ __nv_bfloat16 dsm[];
    __nv_bfloat16* sKh = dsm;
    __nv_bfloat16* sKl = dsm + 128 * KST;
    __half* sV = (__half*)(dsm + 2 * 128 * KST);
    const uint32_t uKh = smem_u32(sKh), uKl = smem_u32(sKl), uV = smem_u32(sV);

    const int tid = threadIdx.x, lid = tid & 31, w = tid >> 5;
    const int q0 = blockIdx.x * 256, bh = blockIdx.y;
    const int g = lid >> 2, t = lid & 3;
    const size_t qkBase = (size_t)bh * 2048 * 64;
    const size_t vBase = (size_t)bh * 131072;

    // Q fragments for this warp's 16 rows (resident whole kernel)
    uint32_t qh[4][4], ql[4][4];
    {
        const __nv_bfloat16* Qh = g_qhi + qkBase + (size_t)(q0 + w * 16) * 64;
        const __nv_bfloat16* Ql = g_qlo + qkBase + (size_t)(q0 + w * 16) * 64;
#pragma unroll
        for (int kk = 0; kk < 4; kk++) {
            int c0 = kk * 16 + 2 * t;
            qh[kk][0] = *(const uint32_t*)(Qh + g * 64 + c0);
            qh[kk][1] = *(const uint32_t*)(Qh + (g + 8) * 64 + c0);
            qh[kk][2] = *(const uint32_t*)(Qh + g * 64 + c0 + 8);
            qh[kk][3] = *(const uint32_t*)(Qh + (g + 8) * 64 + c0 + 8);
            ql[kk][0] = *(const uint32_t*)(Ql + g * 64 + c0);
            ql[kk][1] = *(const uint32_t*)(Ql + (g + 8) * 64 + c0);
            ql[kk][2] = *(const uint32_t*)(Ql + g * 64 + c0 + 8);
            ql[kk][3] = *(const uint32_t*)(Ql + (g + 8) * 64 + c0 + 8);
        }
    }

    float oacc[8][4];
#pragma unroll
    for (int nf = 0; nf < 8; nf++)
#pragma unroll
        for (int e = 0; e < 4; e++) oacc[nf][e] = 0.0f;

    for (int j = 0; j < 16; j++) {
        __syncthreads();
        {
            const float4* Kh = (const float4*)(g_khi + qkBase + (size_t)j * 128 * 64);
            const float4* Kl = (const float4*)(g_klo + qkBase + (size_t)j * 128 * 64);
#pragma unroll
            for (int it = 0; it < 2; it++) {
                int i = tid + it * 512, r = i >> 3, q = i & 7;
                *(float4*)(sKh + r * KST + q * 8) = Kh[r * 8 + q];
                *(float4*)(sKl + r * KST + q * 8) = Kl[r * 8 + q];
            }
            const float4* V = (const float4*)(g_vh + vBase + (size_t)j * 128);
#pragma unroll
            for (int it = 0; it < 2; it++) {
                int i = tid + it * 512, r = i >> 4, q = i & 15;
                *(float4*)(sV + r * VST + q * 8) = V[r * 256 + q];
            }
        }
        __syncthreads();

        // process S in 4 chunks of 32 columns; PV for that chunk immediately
#pragma unroll
        for (int ck = 0; ck < 4; ck++) {
            float sacc[4][4];
#pragma unroll
            for (int nfl = 0; nfl < 4; nfl++)
#pragma unroll
                for (int e = 0; e < 4; e++) sacc[nfl][e] = 0.0f;

#pragma unroll
            for (int nfl = 0; nfl < 4; nfl++) {
                const int nf = ck * 4 + nfl;
                uint32_t kh[8], kl[8];
                uint32_t b0 = (uint32_t)((nf * 8 + (lid & 7)) * KST + (lid >> 3) * 8);
                ldsm4(kh, uKh + b0 * 2);
                ldsm4(kh + 4, uKh + (b0 + 32) * 2);
                ldsm4(kl, uKl + b0 * 2);
                ldsm4(kl + 4, uKl + (b0 + 32) * 2);
#pragma unroll
                for (int kk = 0; kk < 4; kk++) {
                    mma_bf(sacc[nfl], qh[kk], kh + 2 * kk);
                    mma_bf(sacc[nfl], qh[kk], kl + 2 * kk);
                    mma_bf(sacc[nfl], ql[kk], kh + 2 * kk);
                }
            }

            // sigmoid + pack P fragments for this 32-wide k-chunk
            uint32_t ph[2][4];
#pragma unroll
            for (int u = 0; u < 2; u++) {
                float* s0 = sacc[2 * u];
                float* s1 = sacc[2 * u + 1];
                ph[u][0] = packh2(sigmoid_fast(s0[0]), sigmoid_fast(s0[1]));
                ph[u][1] = packh2(sigmoid_fast(s0[2]), sigmoid_fast(s0[3]));
                ph[u][2] = packh2(sigmoid_fast(s1[0]), sigmoid_fast(s1[1]));
                ph[u][3] = packh2(sigmoid_fast(s1[2]), sigmoid_fast(s1[3]));
            }

            // O += P @ V for this k-chunk
#pragma unroll
            for (int nf = 0; nf < 8; nf++) {
                uint32_t vh[4];
                uint32_t o0 =
                    (uint32_t)(((nf * 8 + (lid & 7)) * VST + ck * 32 + (lid >> 3) * 8) * 2);
                ldsm4(vh, uV + o0);
                mma_f16(oacc[nf], ph[0], vh);
                mma_f16(oacc[nf], ph[1], vh + 2);
            }
        }
    }

    // epilogue: split O -> AO scratch [8192, 512]
    {
        const int b = bh >> 3, h = bh & 7;
        const int s = q0 + w * 16 + g;
#pragma unroll
        for (int nf = 0; nf < 8; nf++) {
            int d = nf * 8 + 2 * t;
            uint32_t h01, l01, h23, l23;
            splitpack(oacc[nf][0], oacc[nf][1], h01, l01);
            splitpack(oacc[nf][2], oacc[nf][3], h23, l23);
            size_t o0 = ((size_t)b * 2048 + s) * 512 + h * 64 + d;
            *(uint32_t*)(g_ohi + o0) = h01;
            *(uint32_t*)(g_olo + o0) = l01;
            size_t o1 = o0 + 8 * 512;
            *(uint32_t*)(g_ohi + o1) = h23;
            *(uint32_t*)(g_olo + o1) = l23;
        }
    }
}

// =====================================================================
// Kernel 3: output projection. out[8192,512] = AO @ Wo^T (fp32 out)
// 512 thr, 16 warps 4m x 4n.
// =====================================================================
__global__ __launch_bounds__(512, 1) void k_out(const float* __restrict__ Wo,
                                                float* __restrict__ out) {
    __shared__ __nv_bfloat16 sAh[128 * AST], sAl[128 * AST];
    __shared__ __nv_bfloat16 sBh[128 * AST], sBl[128 * AST];
    const int tid = threadIdx.x, lid = tid & 31, w = tid >> 5;
    const int wm = w >> 2, wn = w & 3;
    const int m0 = blockIdx.x * 128, n0 = blockIdx.y * 128;
    const uint32_t uAh = smem_u32(sAh), uAl = smem_u32(sAl);
    const uint32_t uBh = smem_u32(sBh), uBl = smem_u32(sBl);
    const int g = lid >> 2, t = lid & 3;

    float acc[2][4][4];
#pragma unroll
    for (int mf = 0; mf < 2; mf++)
#pragma unroll
        for (int nf = 0; nf < 4; nf++)
#pragma unroll
            for (int e = 0; e < 4; e++) acc[mf][nf][e] = 0.0f;

    for (int c = 0; c < 16; c++) {
        __syncthreads();
        {
            // A: pre-split bf16, direct copy (128 rows x 32 cols -> 512 float4 x2 arrays)
            const int rA = tid >> 2, qA = tid & 3;
            size_t srcA = (size_t)(m0 + rA) * 64 + c * 4 + qA;
            *(float4*)(sAh + rA * AST + qA * 8) = ((const float4*)g_ohi)[srcA];
            *(float4*)(sAl + rA * AST + qA * 8) = ((const float4*)g_olo)[srcA];
            // B: fp32 Wo, split
            const int rB = tid >> 3, qB = tid & 7;
#pragma unroll
            for (int it = 0; it < 2; it++) {
                float4 f = ((const float4*)Wo)[(size_t)(n0 + rB + it * 64) * 128 + c * 8 + qB];
                uint32_t h0, l0, h1, l1;
                splitpack(f.x, f.y, h0, l0);
                splitpack(f.z, f.w, h1, l1);
                *(uint2*)(sBh + (rB + it * 64) * AST + qB * 4) = make_uint2(h0, h1);
                *(uint2*)(sBl + (rB + it * 64) * AST + qB * 4) = make_uint2(l0, l1);
            }
        }
        __syncthreads();

        uint32_t ah[2][2][4], al[2][2][4];
#pragma unroll
        for (int mf = 0; mf < 2; mf++)
#pragma unroll
            for (int kk = 0; kk < 2; kk++) {
                uint32_t off = (uint32_t)(((wm * 32 + mf * 16 + (lid & 15)) * AST +
                                           kk * 16 + (lid >> 4) * 8) * 2);
                ldsm4(ah[mf][kk], uAh + off);
                ldsm4(al[mf][kk], uAl + off);
            }
#pragma unroll
        for (int nf = 0; nf < 4; nf++) {
            uint32_t bh[4], bl[4];
            uint32_t off =
                (uint32_t)(((wn * 32 + nf * 8 + (lid & 7)) * AST + (lid >> 3) * 8) * 2);
            ldsm4(bh, uBh + off);
            ldsm4(bl, uBl + off);
#pragma unroll
            for (int mf = 0; mf < 2; mf++)
#pragma unroll
                for (int kk = 0; kk < 2; kk++) {
                    mma_bf(acc[mf][nf], ah[mf][kk], bh + kk * 2);
                    mma_bf(acc[mf][nf], ah[mf][kk], bl + kk * 2);
                    mma_bf(acc[mf][nf], al[mf][kk], bh + kk * 2);
                }
        }
    }

    // epilogue: fp32 direct to output
#pragma unroll
    for (int mf = 0; mf < 2; mf++) {
        int m = m0 + wm * 32 + mf * 16 + g;
#pragma unroll
        for (int nf = 0; nf < 4; nf++) {
            int n = n0 + wn * 32 + nf * 8 + 2 * t;
            float* cc = acc[mf][nf];
            *(float2*)(out + (size_t)m * 512 + n) = make_float2(cc[0], cc[1]);
            *(float2*)(out + (size_t)(m + 8) * 512 + n) = make_float2(cc[2], cc[3]);
        }
    }
}

// =====================================================================
extern "C" void kernel_launch(void* const* d_in, const int* in_sizes, int n_in,
                              void* d_out, int out_size) {
    const float* x = (const float*)d_in[0];
    const float* Wq = (const float*)d_in[1];
    const float* Wk = (const float*)d_in[2];
    const float* Wv = (const float*)d_in[3];
    const float* Wo = (const float*)d_in[4];
    float* out = (float*)d_out;

    cudaFuncSetAttribute(k_attn, cudaFuncAttributeMaxDynamicSharedMemorySize, ATTN_SMEM);

    k_qkv<<<dim3(64, 4, 3), 512>>>(x, Wq, Wk, Wv);
    k_attn<<<dim3(8, 32), 512, ATTN_SMEM>>>();
    k_out<<<dim3(64, 4), 512>>>(Wo, out);
}

// round 7
// speedup vs baseline: 2.4901x; 1.3500x over previous
#include <cuda_runtime.h>
#include <cuda_bf16.h>
#include <cuda_fp16.h>
#include <stdint.h>

#define DI __device__ __forceinline__

// ---------------- scratch (static device globals; no allocation) ----------------
#define SCR_ELEMS (4u * 8u * 2048u * 64u)  // 4,194,304
__device__ __align__(16) __half        g_qh[SCR_ELEMS];  // Q fp16: [B,H,S,D]
__device__ __align__(16) __half        g_kh[SCR_ELEMS];  // K fp16: [B,H,S,D]
__device__ __align__(16) __half        g_vh[SCR_ELEMS];  // V^T fp16: [B,H,D,S]
__device__ __align__(16) __nv_bfloat16 g_ohi[SCR_ELEMS]; // AO hi: [8192, 512]
__device__ __align__(16) __nv_bfloat16 g_olo[SCR_ELEMS]; // AO lo: [8192, 512]

// ---------------- helpers ----------------
DI uint32_t smem_u32(const void* p) {
    uint32_t a;
    asm("{ .reg .u64 t; cvta.to.shared.u64 t, %1; cvt.u32.u64 %0, t; }" : "=r"(a) : "l"(p));
    return a;
}
DI void ldsm4(uint32_t* r, uint32_t a) {
    asm volatile("ldmatrix.sync.aligned.m8n8.x4.shared.b16 {%0,%1,%2,%3}, [%4];"
                 : "=r"(r[0]), "=r"(r[1]), "=r"(r[2]), "=r"(r[3]) : "r"(a));
}
DI void mma_bf(float* c, const uint32_t* a, const uint32_t* b) {
    asm volatile(
        "mma.sync.aligned.m16n8k16.row.col.f32.bf16.bf16.f32 "
        "{%0,%1,%2,%3}, {%4,%5,%6,%7}, {%8,%9}, {%0,%1,%2,%3};"
        : "+f"(c[0]), "+f"(c[1]), "+f"(c[2]), "+f"(c[3])
        : "r"(a[0]), "r"(a[1]), "r"(a[2]), "r"(a[3]), "r"(b[0]), "r"(b[1]));
}
DI void mma_f16(float* c, const uint32_t* a, const uint32_t* b) {
    asm volatile(
        "mma.sync.aligned.m16n8k16.row.col.f32.f16.f16.f32 "
        "{%0,%1,%2,%3}, {%4,%5,%6,%7}, {%8,%9}, {%0,%1,%2,%3};"
        : "+f"(c[0]), "+f"(c[1]), "+f"(c[2]), "+f"(c[3])
        : "r"(a[0]), "r"(a[1]), "r"(a[2]), "r"(a[3]), "r"(b[0]), "r"(b[1]));
}
DI void splitpack(float f0, float f1, uint32_t& ph, uint32_t& pl) {
    __nv_bfloat162 vh, vl;
    vh.x = __float2bfloat16_rn(f0);
    vh.y = __float2bfloat16_rn(f1);
    vl.x = __float2bfloat16_rn(f0 - __bfloat162float(vh.x));
    vl.y = __float2bfloat16_rn(f1 - __bfloat162float(vh.y));
    ph = *reinterpret_cast<uint32_t*>(&vh);
    pl = *reinterpret_cast<uint32_t*>(&vl);
}
// sigmoid(qk/8 - log 2048) = 1 / (1 + 2^(11 - qk*0.125*log2(e)))
DI float sigmoid_fast(float qk) {
    float t = fmaf(qk, -0.18033688011112042f, 11.0f);
    float z;
    asm("ex2.approx.f32 %0, %1;" : "=f"(z) : "f"(t));
    float r;
    asm("rcp.approx.f32 %0, %1;" : "=f"(r) : "f"(1.0f + z));
    return r;
}
DI uint32_t packh2(float a, float b) {
    __half2 h = __floats2half2_rn(a, b);
    return *reinterpret_cast<uint32_t*>(&h);
}

constexpr int AST = 40;  // padded smem row stride (elems)

// =====================================================================
// Kernel 1: QKV projection. C[8192,512] = x @ W^T  (z selects W).
// BM=128 BN=64 BK=32, 256 thr (8 warps 4m x 2n), 2 CTAs/SM, 3-combo.
// =====================================================================
__global__ __launch_bounds__(256, 2) void k_qkv(const float* __restrict__ x,
                                                const float* __restrict__ Wq,
                                                const float* __restrict__ Wk,
                                                const float* __restrict__ Wv) {
    __shared__ __nv_bfloat16 sAh[128 * AST], sAl[128 * AST];
    __shared__ __nv_bfloat16 sBh[64 * AST], sBl[64 * AST];
    const int tid = threadIdx.x, lid = tid & 31, w = tid >> 5;
    const int wm = w >> 1, wn = w & 1;
    const int m0 = blockIdx.x * 128, n0 = blockIdx.y * 64, z = blockIdx.z;
    const float* __restrict__ W = (z == 0) ? Wq : ((z == 1) ? Wk : Wv);
    const uint32_t uAh = smem_u32(sAh), uAl = smem_u32(sAl);
    const uint32_t uBh = smem_u32(sBh), uBl = smem_u32(sBl);
    const int g = lid >> 2, t = lid & 3;

    float acc[2][4][4];
#pragma unroll
    for (int mf = 0; mf < 2; mf++)
#pragma unroll
        for (int nf = 0; nf < 4; nf++)
#pragma unroll
            for (int e = 0; e < 4; e++) acc[mf][nf][e] = 0.0f;

    for (int c = 0; c < 16; c++) {
        __syncthreads();
        {
            const int r = tid >> 3, q = tid & 7;
#pragma unroll
            for (int it = 0; it < 4; it++) {  // A: 128 rows
                float4 f = ((const float4*)x)[(size_t)(m0 + r + it * 32) * 128 + c * 8 + q];
                uint32_t h0, l0, h1, l1;
                splitpack(f.x, f.y, h0, l0);
                splitpack(f.z, f.w, h1, l1);
                *(uint2*)(sAh + (r + it * 32) * AST + q * 4) = make_uint2(h0, h1);
                *(uint2*)(sAl + (r + it * 32) * AST + q * 4) = make_uint2(l0, l1);
            }
#pragma unroll
            for (int it = 0; it < 2; it++) {  // B: 64 rows
                float4 f = ((const float4*)W)[(size_t)(n0 + r + it * 32) * 128 + c * 8 + q];
                uint32_t h0, l0, h1, l1;
                splitpack(f.x, f.y, h0, l0);
                splitpack(f.z, f.w, h1, l1);
                *(uint2*)(sBh + (r + it * 32) * AST + q * 4) = make_uint2(h0, h1);
                *(uint2*)(sBl + (r + it * 32) * AST + q * 4) = make_uint2(l0, l1);
            }
        }
        __syncthreads();

        uint32_t ah[2][2][4], al[2][2][4];
#pragma unroll
        for (int mf = 0; mf < 2; mf++)
#pragma unroll
            for (int kk = 0; kk < 2; kk++) {
                uint32_t off = (uint32_t)(((wm * 32 + mf * 16 + (lid & 15)) * AST +
                                           kk * 16 + (lid >> 4) * 8) * 2);
                ldsm4(ah[mf][kk], uAh + off);
                ldsm4(al[mf][kk], uAl + off);
            }
#pragma unroll
        for (int nf = 0; nf < 4; nf++) {
            uint32_t bh[4], bl[4];
            uint32_t off =
                (uint32_t)(((wn * 32 + nf * 8 + (lid & 7)) * AST + (lid >> 3) * 8) * 2);
            ldsm4(bh, uBh + off);
            ldsm4(bl, uBl + off);
#pragma unroll
            for (int mf = 0; mf < 2; mf++)
#pragma unroll
                for (int kk = 0; kk < 2; kk++) {
                    mma_bf(acc[mf][nf], ah[mf][kk], bh + kk * 2);
                    mma_bf(acc[mf][nf], ah[mf][kk], bl + kk * 2);
                    mma_bf(acc[mf][nf], al[mf][kk], bh + kk * 2);
                }
        }
    }

    // epilogue: Q/K -> fp16 [bh][s][d]; V -> fp16 transposed [bh][d][s]
#pragma unroll
    for (int mf = 0; mf < 2; mf++) {
        int m = m0 + wm * 32 + mf * 16 + g;
        int b = m >> 11, s = m & 2047;
#pragma unroll
        for (int nf = 0; nf < 4; nf++) {
            int n = n0 + wn * 32 + nf * 8 + 2 * t;
            int h = n >> 6, d = n & 63;
            float* cc = acc[mf][nf];
            if (z < 2) {
                __half* dst = (z == 0) ? g_qh : g_kh;
                size_t o0 = ((size_t)(b * 8 + h) * 2048 + s) * 64 + d;
                *(uint32_t*)(dst + o0) = packh2(cc[0], cc[1]);
                *(uint32_t*)(dst + o0 + 512) = packh2(cc[2], cc[3]);  // row s+8
            } else {
                size_t o0 = ((size_t)(b * 8 + h) * 64 + d) * 2048 + s;
                g_vh[o0] = __float2half_rn(cc[0]);
                g_vh[o0 + 2048] = __float2half_rn(cc[1]);
                g_vh[o0 + 8] = __float2half_rn(cc[2]);
                g_vh[o0 + 2056] = __float2half_rn(cc[3]);
            }
        }
    }
}

// =====================================================================
// Kernel 2: fused sigmoid attention. 256 thr, q-tile 128 (8 warps x 16
// rows), 2 CTAs/SM. QK single-fp16, PV single-fp16, fp32 accum.
// =====================================================================
constexpr int KST = 72;   // K-tile smem stride (elems)
constexpr int VST = 136;  // V-tile smem stride (elems)

__global__ __launch_bounds__(256, 2) void k_attn() {
    __shared__ __half sK[128 * KST];
    __shared__ __half sV[64 * VST];
    const uint32_t uK = smem_u32(sK), uV = smem_u32(sV);

    const int tid = threadIdx.x, lid = tid & 31, w = tid >> 5;
    const int q0 = blockIdx.x * 128, bh = blockIdx.y;
    const int g = lid >> 2, t = lid & 3;
    const size_t qkBase = (size_t)bh * 2048 * 64;
    const size_t vBase = (size_t)bh * 131072;

    // Q fragments (fp16) for this warp's 16 rows (resident whole kernel)
    uint32_t qf[4][4];
    {
        const __half* Q = g_qh + qkBase + (size_t)(q0 + w * 16) * 64;
#pragma unroll
        for (int kk = 0; kk < 4; kk++) {
            int c0 = kk * 16 + 2 * t;
            qf[kk][0] = *(const uint32_t*)(Q + g * 64 + c0);
            qf[kk][1] = *(const uint32_t*)(Q + (g + 8) * 64 + c0);
            qf[kk][2] = *(const uint32_t*)(Q + g * 64 + c0 + 8);
            qf[kk][3] = *(const uint32_t*)(Q + (g + 8) * 64 + c0 + 8);
        }
    }

    float oacc[8][4];
#pragma unroll
    for (int nf = 0; nf < 8; nf++)
#pragma unroll
        for (int e = 0; e < 4; e++) oacc[nf][e] = 0.0f;

    for (int j = 0; j < 16; j++) {
        __syncthreads();
        {
            const float4* K = (const float4*)(g_kh + qkBase + (size_t)j * 128 * 64);
#pragma unroll
            for (int it = 0; it < 4; it++) {
                int i = tid + it * 256, r = i >> 3, q = i & 7;
                *(float4*)(sK + r * KST + q * 8) = K[r * 8 + q];
            }
            const float4* V = (const float4*)(g_vh + vBase + (size_t)j * 128);
#pragma unroll
            for (int it = 0; it < 4; it++) {
                int i = tid + it * 256, r = i >> 4, q = i & 15;
                *(float4*)(sV + r * VST + q * 8) = V[r * 256 + q];
            }
        }
        __syncthreads();

        // process S in 4 chunks of 32 columns; PV for that chunk immediately
#pragma unroll
        for (int ck = 0; ck < 4; ck++) {
            float sacc[4][4];
#pragma unroll
            for (int nfl = 0; nfl < 4; nfl++)
#pragma unroll
                for (int e = 0; e < 4; e++) sacc[nfl][e] = 0.0f;

#pragma unroll
            for (int nfl = 0; nfl < 4; nfl++) {
                const int nf = ck * 4 + nfl;
                uint32_t kf[8];
                uint32_t b0 = (uint32_t)((nf * 8 + (lid & 7)) * KST + (lid >> 3) * 8);
                ldsm4(kf, uK + b0 * 2);
                ldsm4(kf + 4, uK + (b0 + 32) * 2);
#pragma unroll
                for (int kk = 0; kk < 4; kk++) mma_f16(sacc[nfl], qf[kk], kf + 2 * kk);
            }

            // sigmoid + pack P fragments for this 32-wide k-chunk
            uint32_t ph[2][4];
#pragma unroll
            for (int u = 0; u < 2; u++) {
                float* s0 = sacc[2 * u];
                float* s1 = sacc[2 * u + 1];
                ph[u][0] = packh2(sigmoid_fast(s0[0]), sigmoid_fast(s0[1]));
                ph[u][1] = packh2(sigmoid_fast(s0[2]), sigmoid_fast(s0[3]));
                ph[u][2] = packh2(sigmoid_fast(s1[0]), sigmoid_fast(s1[1]));
                ph[u][3] = packh2(sigmoid_fast(s1[2]), sigmoid_fast(s1[3]));
            }

            // O += P @ V for this k-chunk
#pragma unroll
            for (int nf = 0; nf < 8; nf++) {
                uint32_t vf[4];
                uint32_t o0 =
                    (uint32_t)(((nf * 8 + (lid & 7)) * VST + ck * 32 + (lid >> 3) * 8) * 2);
                ldsm4(vf, uV + o0);
                mma_f16(oacc[nf], ph[0], vf);
                mma_f16(oacc[nf], ph[1], vf + 2);
            }
        }
    }

    // epilogue: split O -> AO scratch [8192, 512] (bf16 hi/lo for k_out)
    {
        const int b = bh >> 3, h = bh & 7;
        const int s = q0 + w * 16 + g;
#pragma unroll
        for (int nf = 0; nf < 8; nf++) {
            int d = nf * 8 + 2 * t;
            uint32_t h01, l01, h23, l23;
            splitpack(oacc[nf][0], oacc[nf][1], h01, l01);
            splitpack(oacc[nf][2], oacc[nf][3], h23, l23);
            size_t o0 = ((size_t)b * 2048 + s) * 512 + h * 64 + d;
            *(uint32_t*)(g_ohi + o0) = h01;
            *(uint32_t*)(g_olo + o0) = l01;
            size_t o1 = o0 + 8 * 512;
            *(uint32_t*)(g_ohi + o1) = h23;
            *(uint32_t*)(g_olo + o1) = l23;
        }
    }
}

// =====================================================================
// Kernel 3: output projection. out[8192,512] = AO @ Wo^T (fp32 out)
// BM=128 BN=64, 256 thr, 2 CTAs/SM, split-bf16 3-combo.
// =====================================================================
__global__ __launch_bounds__(256, 2) void k_out(const float* __restrict__ Wo,
                                                float* __restrict__ out) {
    __shared__ __nv_bfloat16 sAh[128 * AST], sAl[128 * AST];
    __shared__ __nv_bfloat16 sBh[64 * AST], sBl[64 * AST];
    const int tid = threadIdx.x, lid = tid & 31, w = tid >> 5;
    const int wm = w >> 1, wn = w & 1;
    const int m0 = blockIdx.x * 128, n0 = blockIdx.y * 64;
    const uint32_t uAh = smem_u32(sAh), uAl = smem_u32(sAl);
    const uint32_t uBh = smem_u32(sBh), uBl = smem_u32(sBl);
    const int g = lid >> 2, t = lid & 3;

    float acc[2][4][4];
#pragma unroll
    for (int mf = 0; mf < 2; mf++)
#pragma unroll
        for (int nf = 0; nf < 4; nf++)
#pragma unroll
            for (int e = 0; e < 4; e++) acc[mf][nf][e] = 0.0f;

    for (int c = 0; c < 16; c++) {
        __syncthreads();
        {
            // A: pre-split bf16 AO, direct copy (128 rows x 32 cols)
#pragma unroll
            for (int it = 0; it < 2; it++) {
                int i = tid + it * 256, rA = i >> 2, qA = i & 3;
                size_t srcA = (size_t)(m0 + rA) * 64 + c * 4 + qA;
                *(float4*)(sAh + rA * AST + qA * 8) = ((const float4*)g_ohi)[srcA];
                *(float4*)(sAl + rA * AST + qA * 8) = ((const float4*)g_olo)[srcA];
            }
            // B: fp32 Wo (64 rows), split
            {
                const int rB = tid >> 3, qB = tid & 7;
#pragma unroll
                for (int it = 0; it < 2; it++) {
                    float4 f =
                        ((const float4*)Wo)[(size_t)(n0 + rB + it * 32) * 128 + c * 8 + qB];
                    uint32_t h0, l0, h1, l1;
                    splitpack(f.x, f.y, h0, l0);
                    splitpack(f.z, f.w, h1, l1);
                    *(uint2*)(sBh + (rB + it * 32) * AST + qB * 4) = make_uint2(h0, h1);
                    *(uint2*)(sBl + (rB + it * 32) * AST + qB * 4) = make_uint2(l0, l1);
                }
            }
        }
        __syncthreads();

        uint32_t ah[2][2][4], al[2][2][4];
#pragma unroll
        for (int mf = 0; mf < 2; mf++)
#pragma unroll
            for (int kk = 0; kk < 2; kk++) {
                uint32_t off = (uint32_t)(((wm * 32 + mf * 16 + (lid & 15)) * AST +
                                           kk * 16 + (lid >> 4) * 8) * 2);
                ldsm4(ah[mf][kk], uAh + off);
                ldsm4(al[mf][kk], uAl + off);
            }
#pragma unroll
        for (int nf = 0; nf < 4; nf++) {
            uint32_t bh[4], bl[4];
            uint32_t off =
                (uint32_t)(((wn * 32 + nf * 8 + (lid & 7)) * AST + (lid >> 3) * 8) * 2);
            ldsm4(bh, uBh + off);
            ldsm4(bl, uBl + off);
#pragma unroll
            for (int mf = 0; mf < 2; mf++)
#pragma unroll
                for (int kk = 0; kk < 2; kk++) {
                    mma_bf(acc[mf][nf], ah[mf][kk], bh + kk * 2);
                    mma_bf(acc[mf][nf], ah[mf][kk], bl + kk * 2);
                    mma_bf(acc[mf][nf], al[mf][kk], bh + kk * 2);
                }
        }
    }

    // epilogue: fp32 direct to output
#pragma unroll
    for (int mf = 0; mf < 2; mf++) {
        int m = m0 + wm * 32 + mf * 16 + g;
#pragma unroll
        for (int nf = 0; nf < 4; nf++) {
            int n = n0 + wn * 32 + nf * 8 + 2 * t;
            float* cc = acc[mf][nf];
            *(float2*)(out + (size_t)m * 512 + n) = make_float2(cc[0], cc[1]);
            *(float2*)(out + (size_t)(m + 8) * 512 + n) = make_float2(cc[2], cc[3]);
        }
    }
}

// =====================================================================
extern "C" void kernel_launch(void* const* d_in, const int* in_sizes, int n_in,
                              void* d_out, int out_size) {
    const float* x = (const float*)d_in[0];
    const float* Wq = (const float*)d_in[1];
    const float* Wk = (const float*)d_in[2];
    const float* Wv = (const float*)d_in[3];
    const float* Wo = (const float*)d_in[4];
    float* out = (float*)d_out;

    k_qkv<<<dim3(64, 8, 3), 256>>>(x, Wq, Wk, Wv);
    k_attn<<<dim3(16, 32), 256>>>();
    k_out<<<dim3(64, 8), 256>>>(Wo, out);
}

// round 8
// speedup vs baseline: 2.5551x; 1.0261x over previous
#include <cuda_runtime.h>
#include <cuda_bf16.h>
#include <cuda_fp16.h>
#include <stdint.h>

#define DI __device__ __forceinline__

// ---------------- scratch (static device globals; no allocation) ----------------
#define SCR_ELEMS (4u * 8u * 2048u * 64u)  // 4,194,304
__device__ __align__(16) __half g_qh[SCR_ELEMS];  // Q fp16: [B,H,S,D]
__device__ __align__(16) __half g_kh[SCR_ELEMS];  // K fp16: [B,H,S,D]
__device__ __align__(16) __half g_vh[SCR_ELEMS];  // V^T fp16: [B,H,D,S]
__device__ __align__(16) __half g_oh[SCR_ELEMS];  // AO hi fp16: [8192, 512]
__device__ __align__(16) __half g_ol[SCR_ELEMS];  // AO lo fp16: [8192, 512]
__device__ __align__(16) __half g_xh[SCR_ELEMS];  // x hi fp16: [8192, 512]
__device__ __align__(16) __half g_xl[SCR_ELEMS];  // x lo fp16: [8192, 512]

// ---------------- helpers ----------------
DI uint32_t smem_u32(const void* p) {
    uint32_t a;
    asm("{ .reg .u64 t; cvta.to.shared.u64 t, %1; cvt.u32.u64 %0, t; }" : "=r"(a) : "l"(p));
    return a;
}
DI void ldsm4(uint32_t* r, uint32_t a) {
    asm volatile("ldmatrix.sync.aligned.m8n8.x4.shared.b16 {%0,%1,%2,%3}, [%4];"
                 : "=r"(r[0]), "=r"(r[1]), "=r"(r[2]), "=r"(r[3]) : "r"(a));
}
DI void mma_f16(float* c, const uint32_t* a, const uint32_t* b) {
    asm volatile(
        "mma.sync.aligned.m16n8k16.row.col.f32.f16.f16.f32 "
        "{%0,%1,%2,%3}, {%4,%5,%6,%7}, {%8,%9}, {%0,%1,%2,%3};"
        : "+f"(c[0]), "+f"(c[1]), "+f"(c[2]), "+f"(c[3])
        : "r"(a[0]), "r"(a[1]), "r"(a[2]), "r"(a[3]), "r"(b[0]), "r"(b[1]));
}
DI uint32_t packh2(float a, float b) {
    __half2 h = __floats2half2_rn(a, b);
    return *reinterpret_cast<uint32_t*>(&h);
}
// split two floats into fp16 hi + fp16 lo (residual) packed words
DI void splitpackh(float f0, float f1, uint32_t& ph, uint32_t& pl) {
    __half2 vh = __floats2half2_rn(f0, f1);
    __half2 vl = __floats2half2_rn(f0 - __half2float(vh.x), f1 - __half2float(vh.y));
    ph = *reinterpret_cast<uint32_t*>(&vh);
    pl = *reinterpret_cast<uint32_t*>(&vl);
}
// sigmoid(qk/8 - log 2048) = 1 / (1 + 2^(11 - qk*0.125*log2(e)))
DI float sigmoid_fast(float qk) {
    float t = fmaf(qk, -0.18033688011112042f, 11.0f);
    float z;
    asm("ex2.approx.f32 %0, %1;" : "=f"(z) : "f"(t));
    float r;
    asm("rcp.approx.f32 %0, %1;" : "=f"(r) : "f"(1.0f + z));
    return r;
}

constexpr int AST = 40;  // padded smem row stride (elems)

// =====================================================================
// Kernel 0: pre-split x into fp16 hi/lo. 1M float4 chunks.
// =====================================================================
__global__ __launch_bounds__(256) void k_splitx(const float* __restrict__ x) {
    size_t idx = (size_t)blockIdx.x * 256 + threadIdx.x;
    float4 f = ((const float4*)x)[idx];
    uint32_t h01, l01, h23, l23;
    splitpackh(f.x, f.y, h01, l01);
    splitpackh(f.z, f.w, h23, l23);
    ((uint2*)g_xh)[idx] = make_uint2(h01, h23);
    ((uint2*)g_xl)[idx] = make_uint2(l01, l23);
}

// =====================================================================
// Kernel 1: QKV projection. C[8192,512] = x @ W^T  (z selects W).
// BM=128 BN=64 BK=32, 256 thr, 2 CTAs/SM. 2-combo: (xh + xl) @ Wfp16.
// =====================================================================
__global__ __launch_bounds__(256, 2) void k_qkv(const float* __restrict__ Wq,
                                                const float* __restrict__ Wk,
                                                const float* __restrict__ Wv) {
    __shared__ __half sAh[128 * AST], sAl[128 * AST];
    __shared__ __half sB[64 * AST];
    const int tid = threadIdx.x, lid = tid & 31, w = tid >> 5;
    const int wm = w >> 1, wn = w & 1;
    const int m0 = blockIdx.x * 128, n0 = blockIdx.y * 64, z = blockIdx.z;
    const float* __restrict__ W = (z == 0) ? Wq : ((z == 1) ? Wk : Wv);
    const uint32_t uAh = smem_u32(sAh), uAl = smem_u32(sAl), uB = smem_u32(sB);
    const int g = lid >> 2, t = lid & 3;

    float acc[2][4][4];
#pragma unroll
    for (int mf = 0; mf < 2; mf++)
#pragma unroll
        for (int nf = 0; nf < 4; nf++)
#pragma unroll
            for (int e = 0; e < 4; e++) acc[mf][nf][e] = 0.0f;

    for (int c = 0; c < 16; c++) {
        __syncthreads();
        {
            // A: raw fp16 copy (128 rows x 32 cols, hi + lo)
#pragma unroll
            for (int it = 0; it < 2; it++) {
                int i = tid + it * 256, r = i >> 2, q = i & 3;
                size_t src = (size_t)(m0 + r) * 64 + c * 4 + q;
                *(float4*)(sAh + r * AST + q * 8) = ((const float4*)g_xh)[src];
                *(float4*)(sAl + r * AST + q * 8) = ((const float4*)g_xl)[src];
            }
            // B: fp32 W -> single fp16 (64 rows x 32 cols)
#pragma unroll
            for (int it = 0; it < 2; it++) {
                int i = tid + it * 256, r = i >> 3, q = i & 7;
                float4 f = ((const float4*)W)[(size_t)(n0 + r) * 128 + c * 8 + q];
                *(uint2*)(sB + r * AST + q * 4) =
                    make_uint2(packh2(f.x, f.y), packh2(f.z, f.w));
            }
        }
        __syncthreads();

        uint32_t ah[2][2][4], al[2][2][4];
#pragma unroll
        for (int mf = 0; mf < 2; mf++)
#pragma unroll
            for (int kk = 0; kk < 2; kk++) {
                uint32_t off = (uint32_t)(((wm * 32 + mf * 16 + (lid & 15)) * AST +
                                           kk * 16 + (lid >> 4) * 8) * 2);
                ldsm4(ah[mf][kk], uAh + off);
                ldsm4(al[mf][kk], uAl + off);
            }
#pragma unroll
        for (int nf = 0; nf < 4; nf++) {
            uint32_t bf[4];
            uint32_t off =
                (uint32_t)(((wn * 32 + nf * 8 + (lid & 7)) * AST + (lid >> 3) * 8) * 2);
            ldsm4(bf, uB + off);
#pragma unroll
            for (int mf = 0; mf < 2; mf++)
#pragma unroll
                for (int kk = 0; kk < 2; kk++) {
                    mma_f16(acc[mf][nf], ah[mf][kk], bf + kk * 2);
                    mma_f16(acc[mf][nf], al[mf][kk], bf + kk * 2);
                }
        }
    }

    // epilogue: Q/K -> fp16 [bh][s][d]; V -> fp16 transposed [bh][d][s]
#pragma unroll
    for (int mf = 0; mf < 2; mf++) {
        int m = m0 + wm * 32 + mf * 16 + g;
        int b = m >> 11, s = m & 2047;
#pragma unroll
        for (int nf = 0; nf < 4; nf++) {
            int n = n0 + wn * 32 + nf * 8 + 2 * t;
            int h = n >> 6, d = n & 63;
            float* cc = acc[mf][nf];
            if (z < 2) {
                __half* dst = (z == 0) ? g_qh : g_kh;
                size_t o0 = ((size_t)(b * 8 + h) * 2048 + s) * 64 + d;
                *(uint32_t*)(dst + o0) = packh2(cc[0], cc[1]);
                *(uint32_t*)(dst + o0 + 512) = packh2(cc[2], cc[3]);  // row s+8
            } else {
                size_t o0 = ((size_t)(b * 8 + h) * 64 + d) * 2048 + s;
                g_vh[o0] = __float2half_rn(cc[0]);
                g_vh[o0 + 2048] = __float2half_rn(cc[1]);
                g_vh[o0 + 8] = __float2half_rn(cc[2]);
                g_vh[o0 + 2056] = __float2half_rn(cc[3]);
            }
        }
    }
}

// =====================================================================
// Kernel 2: fused sigmoid attention. 256 thr, q-tile 128 (8 warps x 16
// rows), 2 CTAs/SM. QK single-fp16, PV single-fp16, fp32 accum.
// =====================================================================
constexpr int KST = 72;   // K-tile smem stride (elems)
constexpr int VST = 136;  // V-tile smem stride (elems)

__global__ __launch_bounds__(256, 2) void k_attn() {
    __shared__ __half sK[128 * KST];
    __shared__ __half sV[64 * VST];
    const uint32_t uK = smem_u32(sK), uV = smem_u32(sV);

    const int tid = threadIdx.x, lid = tid & 31, w = tid >> 5;
    const int q0 = blockIdx.x * 128, bh = blockIdx.y;
    const int g = lid >> 2, t = lid & 3;
    const size_t qkBase = (size_t)bh * 2048 * 64;
    const size_t vBase = (size_t)bh * 131072;

    // Q fragments (fp16) for this warp's 16 rows (resident whole kernel)
    uint32_t qf[4][4];
    {
        const __half* Q = g_qh + qkBase + (size_t)(q0 + w * 16) * 64;
#pragma unroll
        for (int kk = 0; kk < 4; kk++) {
            int c0 = kk * 16 + 2 * t;
            qf[kk][0] = *(const uint32_t*)(Q + g * 64 + c0);
            qf[kk][1] = *(const uint32_t*)(Q + (g + 8) * 64 + c0);
            qf[kk][2] = *(const uint32_t*)(Q + g * 64 + c0 + 8);
            qf[kk][3] = *(const uint32_t*)(Q + (g + 8) * 64 + c0 + 8);
        }
    }

    float oacc[8][4];
#pragma unroll
    for (int nf = 0; nf < 8; nf++)
#pragma unroll
        for (int e = 0; e < 4; e++) oacc[nf][e] = 0.0f;

    for (int j = 0; j < 16; j++) {
        __syncthreads();
        {
            const float4* K = (const float4*)(g_kh + qkBase + (size_t)j * 128 * 64);
#pragma unroll
            for (int it = 0; it < 4; it++) {
                int i = tid + it * 256, r = i >> 3, q = i & 7;
                *(float4*)(sK + r * KST + q * 8) = K[r * 8 + q];
            }
            const float4* V = (const float4*)(g_vh + vBase + (size_t)j * 128);
#pragma unroll
            for (int it = 0; it < 4; it++) {
                int i = tid + it * 256, r = i >> 4, q = i & 15;
                *(float4*)(sV + r * VST + q * 8) = V[r * 256 + q];
            }
        }
        __syncthreads();

        // process S in 4 chunks of 32 columns; PV for that chunk immediately
#pragma unroll
        for (int ck = 0; ck < 4; ck++) {
            float sacc[4][4];
#pragma unroll
            for (int nfl = 0; nfl < 4; nfl++)
#pragma unroll
                for (int e = 0; e < 4; e++) sacc[nfl][e] = 0.0f;

#pragma unroll
            for (int nfl = 0; nfl < 4; nfl++) {
                const int nf = ck * 4 + nfl;
                uint32_t kf[8];
                uint32_t b0 = (uint32_t)((nf * 8 + (lid & 7)) * KST + (lid >> 3) * 8);
                ldsm4(kf, uK + b0 * 2);
                ldsm4(kf + 4, uK + (b0 + 32) * 2);
#pragma unroll
                for (int kk = 0; kk < 4; kk++) mma_f16(sacc[nfl], qf[kk], kf + 2 * kk);
            }

            // sigmoid + pack P fragments for this 32-wide k-chunk
            uint32_t ph[2][4];
#pragma unroll
            for (int u = 0; u < 2; u++) {
                float* s0 = sacc[2 * u];
                float* s1 = sacc[2 * u + 1];
                ph[u][0] = packh2(sigmoid_fast(s0[0]), sigmoid_fast(s0[1]));
                ph[u][1] = packh2(sigmoid_fast(s0[2]), sigmoid_fast(s0[3]));
                ph[u][2] = packh2(sigmoid_fast(s1[0]), sigmoid_fast(s1[1]));
                ph[u][3] = packh2(sigmoid_fast(s1[2]), sigmoid_fast(s1[3]));
            }

            // O += P @ V for this k-chunk
#pragma unroll
            for (int nf = 0; nf < 8; nf++) {
                uint32_t vf[4];
                uint32_t o0 =
                    (uint32_t)(((nf * 8 + (lid & 7)) * VST + ck * 32 + (lid >> 3) * 8) * 2);
                ldsm4(vf, uV + o0);
                mma_f16(oacc[nf], ph[0], vf);
                mma_f16(oacc[nf], ph[1], vf + 2);
            }
        }
    }

    // epilogue: split O -> AO scratch fp16 hi/lo [8192, 512]
    {
        const int b = bh >> 3, h = bh & 7;
        const int s = q0 + w * 16 + g;
#pragma unroll
        for (int nf = 0; nf < 8; nf++) {
            int d = nf * 8 + 2 * t;
            uint32_t h01, l01, h23, l23;
            splitpackh(oacc[nf][0], oacc[nf][1], h01, l01);
            splitpackh(oacc[nf][2], oacc[nf][3], h23, l23);
            size_t o0 = ((size_t)b * 2048 + s) * 512 + h * 64 + d;
            *(uint32_t*)(g_oh + o0) = h01;
            *(uint32_t*)(g_ol + o0) = l01;
            size_t o1 = o0 + 8 * 512;
            *(uint32_t*)(g_oh + o1) = h23;
            *(uint32_t*)(g_ol + o1) = l23;
        }
    }
}

// =====================================================================
// Kernel 3: output projection. out[8192,512] = AO @ Wo^T (fp32 out)
// BM=128 BN=64, 256 thr, 2 CTAs/SM, 2-combo: (AOh + AOl) @ Wo_fp16.
// =====================================================================
__global__ __launch_bounds__(256, 2) void k_out(const float* __restrict__ Wo,
                                                float* __restrict__ out) {
    __shared__ __half sAh[128 * AST], sAl[128 * AST];
    __shared__ __half sB[64 * AST];
    const int tid = threadIdx.x, lid = tid & 31, w = tid >> 5;
    const int wm = w >> 1, wn = w & 1;
    const int m0 = blockIdx.x * 128, n0 = blockIdx.y * 64;
    const uint32_t uAh = smem_u32(sAh), uAl = smem_u32(sAl), uB = smem_u32(sB);
    const int g = lid >> 2, t = lid & 3;

    float acc[2][4][4];
#pragma unroll
    for (int mf = 0; mf < 2; mf++)
#pragma unroll
        for (int nf = 0; nf < 4; nf++)
#pragma unroll
            for (int e = 0; e < 4; e++) acc[mf][nf][e] = 0.0f;

    for (int c = 0; c < 16; c++) {
        __syncthreads();
        {
#pragma unroll
            for (int it = 0; it < 2; it++) {
                int i = tid + it * 256, r = i >> 2, q = i & 3;
                size_t src = (size_t)(m0 + r) * 64 + c * 4 + q;
                *(float4*)(sAh + r * AST + q * 8) = ((const float4*)g_oh)[src];
                *(float4*)(sAl + r * AST + q * 8) = ((const float4*)g_ol)[src];
            }
#pragma unroll
            for (int it = 0; it < 2; it++) {
                int i = tid + it * 256, r = i >> 3, q = i & 7;
                float4 f = ((const float4*)Wo)[(size_t)(n0 + r) * 128 + c * 8 + q];
                *(uint2*)(sB + r * AST + q * 4) =
                    make_uint2(packh2(f.x, f.y), packh2(f.z, f.w));
            }
        }
        __syncthreads();

        uint32_t ah[2][2][4], al[2][2][4];
#pragma unroll
        for (int mf = 0; mf < 2; mf++)
#pragma unroll
            for (int kk = 0; kk < 2; kk++) {
                uint32_t off = (uint32_t)(((wm * 32 + mf * 16 + (lid & 15)) * AST +
                                           kk * 16 + (lid >> 4) * 8) * 2);
                ldsm4(ah[mf][kk], uAh + off);
                ldsm4(al[mf][kk], uAl + off);
            }
#pragma unroll
        for (int nf = 0; nf < 4; nf++) {
            uint32_t bf[4];
            uint32_t off =
                (uint32_t)(((wn * 32 + nf * 8 + (lid & 7)) * AST + (lid >> 3) * 8) * 2);
            ldsm4(bf, uB + off);
#pragma unroll
            for (int mf = 0; mf < 2; mf++)
#pragma unroll
                for (int kk = 0; kk < 2; kk++) {
                    mma_f16(acc[mf][nf], ah[mf][kk], bf + kk * 2);
                    mma_f16(acc[mf][nf], al[mf][kk], bf + kk * 2);
                }
        }
    }

    // epilogue: fp32 direct to output
#pragma unroll
    for (int mf = 0; mf < 2; mf++) {
        int m = m0 + wm * 32 + mf * 16 + g;
#pragma unroll
        for (int nf = 0; nf < 4; nf++) {
            int n = n0 + wn * 32 + nf * 8 + 2 * t;
            float* cc = acc[mf][nf];
            *(float2*)(out + (size_t)m * 512 + n) = make_float2(cc[0], cc[1]);
            *(float2*)(out + (size_t)(m + 8) * 512 + n) = make_float2(cc[2], cc[3]);
        }
    }
}

// =====================================================================
extern "C" void kernel_launch(void* const* d_in, const int* in_sizes, int n_in,
                              void* d_out, int out_size) {
    const float* x = (const float*)d_in[0];
    const float* Wq = (const float*)d_in[1];
    const float* Wk = (const float*)d_in[2];
    const float* Wv = (const float*)d_in[3];
    const float* Wo = (const float*)d_in[4];
    float* out = (float*)d_out;

    k_splitx<<<4096, 256>>>(x);
    k_qkv<<<dim3(64, 8, 3), 256>>>(Wq, Wk, Wv);
    k_attn<<<dim3(16, 32), 256>>>();
    k_out<<<dim3(64, 8), 256>>>(Wo, out);
}

// round 9
// speedup vs baseline: 3.0993x; 1.2130x over previous
#include <cuda_runtime.h>
#include <cuda_bf16.h>
#include <cuda_fp16.h>
#include <stdint.h>

#define DI __device__ __forceinline__

// ---------------- scratch (static device globals; no allocation) ----------------
#define SCR_ELEMS (4u * 8u * 2048u * 64u)  // 4,194,304
__device__ __align__(16) __half g_qh[SCR_ELEMS];      // Q fp16: [B,H,S,D]
__device__ __align__(16) __half g_kh[SCR_ELEMS];      // K fp16: [B,H,S,D]
__device__ __align__(16) __half g_vh[SCR_ELEMS];      // V^T fp16: [B,H,D,S]
__device__ __align__(16) __half g_oh[SCR_ELEMS];      // AO hi fp16: [8192, 512]
__device__ __align__(16) __half g_ol[SCR_ELEMS];      // AO lo fp16: [8192, 512]
__device__ __align__(16) __half g_xh[SCR_ELEMS];      // x hi fp16: [8192, 512]
__device__ __align__(16) __half g_xl[SCR_ELEMS];      // x lo fp16: [8192, 512]
__device__ __align__(16) __half g_wh[4u * 262144u];   // Wq,Wk,Wv,Wo fp16

// ---------------- helpers ----------------
DI uint32_t smem_u32(const void* p) {
    uint32_t a;
    asm("{ .reg .u64 t; cvta.to.shared.u64 t, %1; cvt.u32.u64 %0, t; }" : "=r"(a) : "l"(p));
    return a;
}
DI void ldsm4(uint32_t* r, uint32_t a) {
    asm volatile("ldmatrix.sync.aligned.m8n8.x4.shared.b16 {%0,%1,%2,%3}, [%4];"
                 : "=r"(r[0]), "=r"(r[1]), "=r"(r[2]), "=r"(r[3]) : "r"(a));
}
DI void mma_f16(float* c, const uint32_t* a, const uint32_t* b) {
    asm volatile(
        "mma.sync.aligned.m16n8k16.row.col.f32.f16.f16.f32 "
        "{%0,%1,%2,%3}, {%4,%5,%6,%7}, {%8,%9}, {%0,%1,%2,%3};"
        : "+f"(c[0]), "+f"(c[1]), "+f"(c[2]), "+f"(c[3])
        : "r"(a[0]), "r"(a[1]), "r"(a[2]), "r"(a[3]), "r"(b[0]), "r"(b[1]));
}
DI void cp16(uint32_t dst, const void* src) {
    asm volatile("cp.async.cg.shared.global [%0], [%1], 16;" :: "r"(dst), "l"(src));
}
DI void cp_commit() { asm volatile("cp.async.commit_group;" ::: "memory"); }
template <int N> DI void cp_wait() { asm volatile("cp.async.wait_group %0;" :: "n"(N) : "memory"); }

DI uint32_t packh2(float a, float b) {
    __half2 h = __floats2half2_rn(a, b);
    return *reinterpret_cast<uint32_t*>(&h);
}
DI void splitpackh(float f0, float f1, uint32_t& ph, uint32_t& pl) {
    __half2 vh = __floats2half2_rn(f0, f1);
    __half2 vl = __floats2half2_rn(f0 - __half2float(vh.x), f1 - __half2float(vh.y));
    ph = *reinterpret_cast<uint32_t*>(&vh);
    pl = *reinterpret_cast<uint32_t*>(&vl);
}
// sigmoid(qk/8 - log 2048) = 1 / (1 + 2^(11 - qk*0.125*log2(e)))
DI float sigmoid_fast(float qk) {
    float t = fmaf(qk, -0.18033688011112042f, 11.0f);
    float z;
    asm("ex2.approx.f32 %0, %1;" : "=f"(z) : "f"(t));
    float r;
    asm("rcp.approx.f32 %0, %1;" : "=f"(r) : "f"(1.0f + z));
    return r;
}

constexpr int AST = 40;  // padded smem row stride (elems)

// =====================================================================
// Kernel 0: pre-split x (fp16 hi/lo) and pre-convert weights (fp16).
// idx space: 1,048,576 float4 (x) + 4*65,536 float4 (weights)
// =====================================================================
__global__ __launch_bounds__(256) void k_split(const float* __restrict__ x,
                                               const float* __restrict__ Wq,
                                               const float* __restrict__ Wk,
                                               const float* __restrict__ Wv,
                                               const float* __restrict__ Wo) {
    size_t idx = (size_t)blockIdx.x * 256 + threadIdx.x;
    if (idx < 1048576) {
        float4 f = ((const float4*)x)[idx];
        uint32_t h01, l01, h23, l23;
        splitpackh(f.x, f.y, h01, l01);
        splitpackh(f.z, f.w, h23, l23);
        ((uint2*)g_xh)[idx] = make_uint2(h01, h23);
        ((uint2*)g_xl)[idx] = make_uint2(l01, l23);
    } else {
        size_t r = idx - 1048576;
        int ws = (int)(r >> 16);
        size_t off = r & 65535;
        const float* src = (ws == 0) ? Wq : (ws == 1) ? Wk : (ws == 2) ? Wv : Wo;
        float4 f = ((const float4*)src)[off];
        ((uint2*)(g_wh + (size_t)ws * 262144))[off] =
            make_uint2(packh2(f.x, f.y), packh2(f.z, f.w));
    }
}

// =====================================================================
// Shared proj-GEMM: BM=128 BN=64 BK=32, 256 thr (8 warps 4m x 2n),
// 2 CTAs/SM, 3-stage cp.async ring, 2-combo (Ah + Al) @ B_fp16.
// stage layout (elems): A_hi [0,5120) A_lo [5120,10240) B [10240,12800)
// =====================================================================
constexpr int PST = 12800;                 // stage elems
constexpr int PROJ_SMEM = 3 * PST * 2;     // 76800 B

template <typename EPI>
DI void proj_gemm(const __half* __restrict__ Ah, const __half* __restrict__ Al,
                  const __half* __restrict__ B, int m0, int n0, EPI epi) {
    extern __shared__ __half dsm[];
    const uint32_t u0 = smem_u32(dsm);
    const int tid = threadIdx.x, lid = tid & 31, w = tid >> 5;
    const int wm = w >> 1, wn = w & 1;

    auto load_stage = [&](int c, int s) {
        uint32_t base = u0 + (uint32_t)(s * PST * 2);
        {   // A hi/lo: 512 chunks each, 2 per thread
            const int r = tid >> 2, q = tid & 3;
#pragma unroll
            for (int it = 0; it < 2; it++) {
                int rr = r + it * 64;
                size_t src = (size_t)(m0 + rr) * 512 + c * 32 + q * 8;
                uint32_t d = (uint32_t)((rr * AST + q * 8) * 2);
                cp16(base + d, Ah + src);
                cp16(base + 10240 + d, Al + src);
            }
        }
        {   // B: 256 chunks, 1 per thread
            const int r = tid >> 2, q = tid & 3;
            if (r < 64) {
                size_t src = (size_t)(n0 + r) * 512 + c * 32 + q * 8;
                cp16(base + 20480 + (uint32_t)((r * AST + q * 8) * 2), B + src);
            }
        }
    };

    float acc[2][4][4];
#pragma unroll
    for (int mf = 0; mf < 2; mf++)
#pragma unroll
        for (int nf = 0; nf < 4; nf++)
#pragma unroll
            for (int e = 0; e < 4; e++) acc[mf][nf][e] = 0.0f;

    load_stage(0, 0); cp_commit();
    load_stage(1, 1); cp_commit();

    for (int c = 0; c < 16; c++) {
        if (c < 15) cp_wait<1>(); else cp_wait<0>();
        __syncthreads();
        if (c < 14) { load_stage(c + 2, (c + 2) % 3); cp_commit(); }

        const uint32_t bA = u0 + (uint32_t)((c % 3) * PST * 2);
        const uint32_t uAh = bA, uAl = bA + 10240, uB = bA + 20480;

        uint32_t ah[2][2][4], al[2][2][4];
#pragma unroll
        for (int mf = 0; mf < 2; mf++)
#pragma unroll
            for (int kk = 0; kk < 2; kk++) {
                uint32_t off = (uint32_t)(((wm * 32 + mf * 16 + (lid & 15)) * AST +
                                           kk * 16 + (lid >> 4) * 8) * 2);
                ldsm4(ah[mf][kk], uAh + off);
                ldsm4(al[mf][kk], uAl + off);
            }
#pragma unroll
        for (int nf = 0; nf < 4; nf++) {
            uint32_t bf[4];
            uint32_t off =
                (uint32_t)(((wn * 32 + nf * 8 + (lid & 7)) * AST + (lid >> 3) * 8) * 2);
            ldsm4(bf, uB + off);
#pragma unroll
            for (int mf = 0; mf < 2; mf++)
#pragma unroll
                for (int kk = 0; kk < 2; kk++) {
                    mma_f16(acc[mf][nf], ah[mf][kk], bf + kk * 2);
                    mma_f16(acc[mf][nf], al[mf][kk], bf + kk * 2);
                }
        }
    }
    epi(acc);
}

// =====================================================================
// Kernel 1: QKV projection (z selects W). Epilogue -> Q/K fp16, V^T fp16.
// =====================================================================
__global__ __launch_bounds__(256, 2) void k_qkv() {
    const int tid = threadIdx.x, lid = tid & 31, w = tid >> 5;
    const int wm = w >> 1, wn = w & 1;
    const int m0 = blockIdx.x * 128, n0 = blockIdx.y * 64, z = blockIdx.z;
    const int g = lid >> 2, t = lid & 3;

    proj_gemm(g_xh, g_xl, g_wh + (size_t)z * 262144, m0, n0, [&](float acc[2][4][4]) {
#pragma unroll
        for (int mf = 0; mf < 2; mf++) {
            int m = m0 + wm * 32 + mf * 16 + g;
            int b = m >> 11, s = m & 2047;
#pragma unroll
            for (int nf = 0; nf < 4; nf++) {
                int n = n0 + wn * 32 + nf * 8 + 2 * t;
                int h = n >> 6, d = n & 63;
                float* cc = acc[mf][nf];
                if (z < 2) {
                    __half* dst = (z == 0) ? g_qh : g_kh;
                    size_t o0 = ((size_t)(b * 8 + h) * 2048 + s) * 64 + d;
                    *(uint32_t*)(dst + o0) = packh2(cc[0], cc[1]);
                    *(uint32_t*)(dst + o0 + 512) = packh2(cc[2], cc[3]);  // row s+8
                } else {
                    size_t o0 = ((size_t)(b * 8 + h) * 64 + d) * 2048 + s;
                    g_vh[o0] = __float2half_rn(cc[0]);
                    g_vh[o0 + 2048] = __float2half_rn(cc[1]);
                    g_vh[o0 + 8] = __float2half_rn(cc[2]);
                    g_vh[o0 + 2056] = __float2half_rn(cc[3]);
                }
            }
        }
    });
}

// =====================================================================
// Kernel 3: output projection. Epilogue -> fp32 out.
// =====================================================================
__global__ __launch_bounds__(256, 2) void k_out(float* __restrict__ out) {
    const int tid = threadIdx.x, lid = tid & 31, w = tid >> 5;
    const int wm = w >> 1, wn = w & 1;
    const int m0 = blockIdx.x * 128, n0 = blockIdx.y * 64;
    const int g = lid >> 2, t = lid & 3;

    proj_gemm(g_oh, g_ol, g_wh + 3u * 262144, m0, n0, [&](float acc[2][4][4]) {
#pragma unroll
        for (int mf = 0; mf < 2; mf++) {
            int m = m0 + wm * 32 + mf * 16 + g;
#pragma unroll
            for (int nf = 0; nf < 4; nf++) {
                int n = n0 + wn * 32 + nf * 8 + 2 * t;
                float* cc = acc[mf][nf];
                *(float2*)(out + (size_t)m * 512 + n) = make_float2(cc[0], cc[1]);
                *(float2*)(out + (size_t)(m + 8) * 512 + n) = make_float2(cc[2], cc[3]);
            }
        }
    });
}

// =====================================================================
// Kernel 2: fused sigmoid attention. 256 thr, q-tile 128 (8 warps x 16
// rows), 2 CTAs/SM, 3-stage cp.async ring over kv tiles.
// stage layout (elems): K [0,9216) V [9216,17920)
// =====================================================================
constexpr int KST = 72;                    // K-tile smem stride (elems)
constexpr int VST = 136;                   // V-tile smem stride (elems)
constexpr int TST = 17920;                 // stage elems
constexpr int ATTN_SMEM = 3 * TST * 2;     // 107520 B

__global__ __launch_bounds__(256, 2) void k_attn() {
    extern __shared__ __half dsm[];
    const uint32_t u0 = smem_u32(dsm);
    const int tid = threadIdx.x, lid = tid & 31, w = tid >> 5;
    const int q0 = blockIdx.x * 128, bh = blockIdx.y;
    const int g = lid >> 2, t = lid & 3;
    const size_t qkBase = (size_t)bh * 2048 * 64;
    const size_t vBase = (size_t)bh * 131072;

    auto load_stage = [&](int j, int s) {
        uint32_t base = u0 + (uint32_t)(s * TST * 2);
        {   // K: 128 rows x 64 cols = 1024 chunks, 4 per thread
            const int r0 = tid >> 3, q = tid & 7;
#pragma unroll
            for (int it = 0; it < 4; it++) {
                int r = r0 + it * 32;
                size_t src = qkBase + (size_t)(j * 128 + r) * 64 + q * 8;
                cp16(base + (uint32_t)((r * KST + q * 8) * 2), g_kh + src);
            }
        }
        {   // V: 64 rows x 128 cols = 1024 chunks, 4 per thread
            const int r0 = tid >> 4, q = tid & 15;
#pragma unroll
            for (int it = 0; it < 4; it++) {
                int r = r0 + it * 16;
                size_t src = vBase + (size_t)j * 128 + (size_t)r * 2048 + q * 8;
                cp16(base + 18432 + (uint32_t)((r * VST + q * 8) * 2), g_vh + src);
            }
        }
    };

    load_stage(0, 0); cp_commit();
    load_stage(1, 1); cp_commit();

    // Q fragments (fp16) for this warp's 16 rows (resident whole kernel)
    uint32_t qf[4][4];
    {
        const __half* Q = g_qh + qkBase + (size_t)(q0 + w * 16) * 64;
#pragma unroll
        for (int kk = 0; kk < 4; kk++) {
            int c0 = kk * 16 + 2 * t;
            qf[kk][0] = *(const uint32_t*)(Q + g * 64 + c0);
            qf[kk][1] = *(const uint32_t*)(Q + (g + 8) * 64 + c0);
            qf[kk][2] = *(const uint32_t*)(Q + g * 64 + c0 + 8);
            qf[kk][3] = *(const uint32_t*)(Q + (g + 8) * 64 + c0 + 8);
        }
    }

    float oacc[8][4];
#pragma unroll
    for (int nf = 0; nf < 8; nf++)
#pragma unroll
        for (int e = 0; e < 4; e++) oacc[nf][e] = 0.0f;

    for (int j = 0; j < 16; j++) {
        if (j < 15) cp_wait<1>(); else cp_wait<0>();
        __syncthreads();
        if (j < 14) { load_stage(j + 2, (j + 2) % 3); cp_commit(); }

        const uint32_t base = u0 + (uint32_t)((j % 3) * TST * 2);
        const uint32_t uK = base, uV = base + 18432;

        // process S in 4 chunks of 32 columns; PV for that chunk immediately
#pragma unroll
        for (int ck = 0; ck < 4; ck++) {
            float sacc[4][4];
#pragma unroll
            for (int nfl = 0; nfl < 4; nfl++)
#pragma unroll
                for (int e = 0; e < 4; e++) sacc[nfl][e] = 0.0f;

#pragma unroll
            for (int nfl = 0; nfl < 4; nfl++) {
                const int nf = ck * 4 + nfl;
                uint32_t kf[8];
                uint32_t b0 = (uint32_t)((nf * 8 + (lid & 7)) * KST + (lid >> 3) * 8);
                ldsm4(kf, uK + b0 * 2);
                ldsm4(kf + 4, uK + (b0 + 32) * 2);
#pragma unroll
                for (int kk = 0; kk < 4; kk++) mma_f16(sacc[nfl], qf[kk], kf + 2 * kk);
            }

            // sigmoid + pack P fragments for this 32-wide k-chunk
            uint32_t ph[2][4];
#pragma unroll
            for (int u = 0; u < 2; u++) {
                float* s0 = sacc[2 * u];
                float* s1 = sacc[2 * u + 1];
                ph[u][0] = packh2(sigmoid_fast(s0[0]), sigmoid_fast(s0[1]));
                ph[u][1] = packh2(sigmoid_fast(s0[2]), sigmoid_fast(s0[3]));
                ph[u][2] = packh2(sigmoid_fast(s1[0]), sigmoid_fast(s1[1]));
                ph[u][3] = packh2(sigmoid_fast(s1[2]), sigmoid_fast(s1[3]));
            }

            // O += P @ V for this k-chunk
#pragma unroll
            for (int nf = 0; nf < 8; nf++) {
                uint32_t vf[4];
                uint32_t o0 =
                    (uint32_t)(((nf * 8 + (lid & 7)) * VST + ck * 32 + (lid >> 3) * 8) * 2);
                ldsm4(vf, uV + o0);
                mma_f16(oacc[nf], ph[0], vf);
                mma_f16(oacc[nf], ph[1], vf + 2);
            }
        }
    }

    // epilogue: split O -> AO scratch fp16 hi/lo [8192, 512]
    {
        const int b = bh >> 3, h = bh & 7;
        const int s = q0 + w * 16 + g;
#pragma unroll
        for (int nf = 0; nf < 8; nf++) {
            int d = nf * 8 + 2 * t;
            uint32_t h01, l01, h23, l23;
            splitpackh(oacc[nf][0], oacc[nf][1], h01, l01);
            splitpackh(oacc[nf][2], oacc[nf][3], h23, l23);
            size_t o0 = ((size_t)b * 2048 + s) * 512 + h * 64 + d;
            *(uint32_t*)(g_oh + o0) = h01;
            *(uint32_t*)(g_ol + o0) = l01;
            size_t o1 = o0 + 8 * 512;
            *(uint32_t*)(g_oh + o1) = h23;
            *(uint32_t*)(g_ol + o1) = l23;
        }
    }
}

// =====================================================================
extern "C" void kernel_launch(void* const* d_in, const int* in_sizes, int n_in,
                              void* d_out, int out_size) {
    const float* x = (const float*)d_in[0];
    const float* Wq = (const float*)d_in[1];
    const float* Wk = (const float*)d_in[2];
    const float* Wv = (const float*)d_in[3];
    const float* Wo = (const float*)d_in[4];
    float* out = (float*)d_out;

    cudaFuncSetAttribute(k_qkv, cudaFuncAttributeMaxDynamicSharedMemorySize, PROJ_SMEM);
    cudaFuncSetAttribute(k_out, cudaFuncAttributeMaxDynamicSharedMemorySize, PROJ_SMEM);
    cudaFuncSetAttribute(k_attn, cudaFuncAttributeMaxDynamicSharedMemorySize, ATTN_SMEM);

    k_split<<<5120, 256>>>(x, Wq, Wk, Wv, Wo);
    k_qkv<<<dim3(64, 8, 3), 256, PROJ_SMEM>>>();
    k_attn<<<dim3(16, 32), 256, ATTN_SMEM>>>();
    k_out<<<dim3(64, 8), 256, PROJ_SMEM>>>(out);
}

// round 10
// speedup vs baseline: 3.5095x; 1.1323x over previous
#include <cuda_runtime.h>
#include <cuda_bf16.h>
#include <cuda_fp16.h>
#include <stdint.h>

#define DI __device__ __forceinline__

// ---------------- scratch (static device globals; no allocation) ----------------
#define SCR_ELEMS (4u * 8u * 2048u * 64u)  // 4,194,304
__device__ __align__(16) __half g_qh[SCR_ELEMS];      // Q fp16: [B,H,S,D]
__device__ __align__(16) __half g_kh[SCR_ELEMS];      // K fp16: [B,H,S,D]
__device__ __align__(16) __half g_vh[SCR_ELEMS];      // V^T fp16: [B,H,D,S]
__device__ __align__(16) __half g_oh[SCR_ELEMS];      // AO hi fp16: [8192, 512]
__device__ __align__(16) __half g_ol[SCR_ELEMS];      // AO lo fp16: [8192, 512]
__device__ __align__(16) __half g_xh[SCR_ELEMS];      // x hi fp16: [8192, 512]
__device__ __align__(16) __half g_xl[SCR_ELEMS];      // x lo fp16: [8192, 512]
__device__ __align__(16) __half g_wh[4u * 262144u];   // Wq,Wk,Wv,Wo fp16

// ---------------- helpers ----------------
DI uint32_t smem_u32(const void* p) {
    uint32_t a;
    asm("{ .reg .u64 t; cvta.to.shared.u64 t, %1; cvt.u32.u64 %0, t; }" : "=r"(a) : "l"(p));
    return a;
}
DI void ldsm4(uint32_t* r, uint32_t a) {
    asm volatile("ldmatrix.sync.aligned.m8n8.x4.shared.b16 {%0,%1,%2,%3}, [%4];"
                 : "=r"(r[0]), "=r"(r[1]), "=r"(r[2]), "=r"(r[3]) : "r"(a));
}
DI void mma_f16(float* c, const uint32_t* a, const uint32_t* b) {
    asm volatile(
        "mma.sync.aligned.m16n8k16.row.col.f32.f16.f16.f32 "
        "{%0,%1,%2,%3}, {%4,%5,%6,%7}, {%8,%9}, {%0,%1,%2,%3};"
        : "+f"(c[0]), "+f"(c[1]), "+f"(c[2]), "+f"(c[3])
        : "r"(a[0]), "r"(a[1]), "r"(a[2]), "r"(a[3]), "r"(b[0]), "r"(b[1]));
}
DI void cp16(uint32_t dst, const void* src) {
    asm volatile("cp.async.cg.shared.global [%0], [%1], 16;" :: "r"(dst), "l"(src));
}
DI void cp_commit() { asm volatile("cp.async.commit_group;" ::: "memory"); }
template <int N> DI void cp_wait() { asm volatile("cp.async.wait_group %0;" :: "n"(N) : "memory"); }

DI uint32_t packh2(float a, float b) {
    __half2 h = __floats2half2_rn(a, b);
    return *reinterpret_cast<uint32_t*>(&h);
}
DI void splitpackh(float f0, float f1, uint32_t& ph, uint32_t& pl) {
    __half2 vh = __floats2half2_rn(f0, f1);
    __half2 vl = __floats2half2_rn(f0 - __half2float(vh.x), f1 - __half2float(vh.y));
    ph = *reinterpret_cast<uint32_t*>(&vh);
    pl = *reinterpret_cast<uint32_t*>(&vl);
}
// sigmoid(qk/8 - log 2048) = 0.5 + 0.5*tanh((qk/8 - log2048)/2)  — single MUFU
DI float sigmoid_tanh(float qk) {
    float t = fmaf(qk, 0.0625f, -3.81230949f);  // qk/16 - log(2048)/2
    float th;
    asm("tanh.approx.f32 %0, %1;" : "=f"(th) : "f"(t));
    return fmaf(th, 0.5f, 0.5f);
}

// =====================================================================
// Kernel 0: pre-split x (fp16 hi/lo) and pre-convert weights (fp16).
// =====================================================================
__global__ __launch_bounds__(256) void k_split(const float* __restrict__ x,
                                               const float* __restrict__ Wq,
                                               const float* __restrict__ Wk,
                                               const float* __restrict__ Wv,
                                               const float* __restrict__ Wo) {
    size_t idx = (size_t)blockIdx.x * 256 + threadIdx.x;
    if (idx < 1048576) {
        float4 f = ((const float4*)x)[idx];
        uint32_t h01, l01, h23, l23;
        splitpackh(f.x, f.y, h01, l01);
        splitpackh(f.z, f.w, h23, l23);
        ((uint2*)g_xh)[idx] = make_uint2(h01, h23);
        ((uint2*)g_xl)[idx] = make_uint2(l01, l23);
    } else {
        size_t r = idx - 1048576;
        int ws = (int)(r >> 16);
        size_t off = r & 65535;
        const float* src = (ws == 0) ? Wq : (ws == 1) ? Wk : (ws == 2) ? Wv : Wo;
        float4 f = ((const float4*)src)[off];
        ((uint2*)(g_wh + (size_t)ws * 262144))[off] =
            make_uint2(packh2(f.x, f.y), packh2(f.z, f.w));
    }
}

// =====================================================================
// Shared proj-GEMM: BM=128 BN=64 BK=64, 256 thr (8 warps 4m x 2n),
// 2 CTAs/SM, 2-stage cp.async ring (load issued after barrier),
// 2-combo (Ah + Al) @ B_fp16.
// stage layout (elems): A_hi [0,9216) A_lo [9216,18432) B [18432,23040)
// =====================================================================
constexpr int RST = 72;                    // padded row stride (elems) for 64-col tiles
constexpr int PST = 23040;                 // stage elems
constexpr int PROJ_SMEM = 2 * PST * 2;     // 92160 B

template <typename EPI>
DI void proj_gemm(const __half* __restrict__ Ah, const __half* __restrict__ Al,
                  const __half* __restrict__ B, int m0, int n0, EPI epi) {
    extern __shared__ __half dsm[];
    const uint32_t u0 = smem_u32(dsm);
    const int tid = threadIdx.x, lid = tid & 31, w = tid >> 5;
    const int wm = w >> 1, wn = w & 1;

    auto load_stage = [&](int c, int s) {
        uint32_t base = u0 + (uint32_t)(s * PST * 2);
        const int r0 = tid >> 3, q = tid & 7;
        // A hi/lo: 128 rows x 64 cols
#pragma unroll
        for (int it = 0; it < 4; it++) {
            int r = r0 + it * 32;
            size_t src = (size_t)(m0 + r) * 512 + c * 64 + q * 8;
            uint32_t d = (uint32_t)((r * RST + q * 8) * 2);
            cp16(base + d, Ah + src);
            cp16(base + 18432 + d, Al + src);
        }
        // B: 64 rows x 64 cols
#pragma unroll
        for (int it = 0; it < 2; it++) {
            int r = r0 + it * 32;
            size_t src = (size_t)(n0 + r) * 512 + c * 64 + q * 8;
            cp16(base + 36864 + (uint32_t)((r * RST + q * 8) * 2), B + src);
        }
    };

    float acc[2][4][4];
#pragma unroll
    for (int mf = 0; mf < 2; mf++)
#pragma unroll
        for (int nf = 0; nf < 4; nf++)
#pragma unroll
            for (int e = 0; e < 4; e++) acc[mf][nf][e] = 0.0f;

    load_stage(0, 0);
    cp_commit();

    for (int c = 0; c < 8; c++) {
        cp_wait<0>();
        __syncthreads();
        if (c < 7) { load_stage(c + 1, (c + 1) & 1); cp_commit(); }

        const uint32_t bA = u0 + (uint32_t)((c & 1) * PST * 2);
        const uint32_t uAh = bA, uAl = bA + 18432, uB = bA + 36864;

#pragma unroll
        for (int kh = 0; kh < 2; kh++) {
            uint32_t ah[2][2][4], al[2][2][4];
#pragma unroll
            for (int mf = 0; mf < 2; mf++)
#pragma unroll
                for (int kk = 0; kk < 2; kk++) {
                    uint32_t off = (uint32_t)(((wm * 32 + mf * 16 + (lid & 15)) * RST +
                                               kh * 32 + kk * 16 + (lid >> 4) * 8) * 2);
                    ldsm4(ah[mf][kk], uAh + off);
                    ldsm4(al[mf][kk], uAl + off);
                }
#pragma unroll
            for (int nf = 0; nf < 4; nf++) {
                uint32_t bf[4];
                uint32_t off = (uint32_t)(((wn * 32 + nf * 8 + (lid & 7)) * RST +
                                           kh * 32 + (lid >> 3) * 8) * 2);
                ldsm4(bf, uB + off);
#pragma unroll
                for (int mf = 0; mf < 2; mf++)
#pragma unroll
                    for (int kk = 0; kk < 2; kk++) {
                        mma_f16(acc[mf][nf], ah[mf][kk], bf + kk * 2);
                        mma_f16(acc[mf][nf], al[mf][kk], bf + kk * 2);
                    }
            }
        }
    }
    epi(acc);
}

// =====================================================================
// Kernel 1: QKV projection (z selects W). Epilogue -> Q/K fp16, V^T fp16.
// =====================================================================
__global__ __launch_bounds__(256, 2) void k_qkv() {
    const int tid = threadIdx.x, lid = tid & 31, w = tid >> 5;
    const int wm = w >> 1, wn = w & 1;
    const int m0 = blockIdx.x * 128, n0 = blockIdx.y * 64, z = blockIdx.z;
    const int g = lid >> 2, t = lid & 3;

    proj_gemm(g_xh, g_xl, g_wh + (size_t)z * 262144, m0, n0, [&](float acc[2][4][4]) {
#pragma unroll
        for (int mf = 0; mf < 2; mf++) {
            int m = m0 + wm * 32 + mf * 16 + g;
            int b = m >> 11, s = m & 2047;
#pragma unroll
            for (int nf = 0; nf < 4; nf++) {
                int n = n0 + wn * 32 + nf * 8 + 2 * t;
                int h = n >> 6, d = n & 63;
                float* cc = acc[mf][nf];
                if (z < 2) {
                    __half* dst = (z == 0) ? g_qh : g_kh;
                    size_t o0 = ((size_t)(b * 8 + h) * 2048 + s) * 64 + d;
                    *(uint32_t*)(dst + o0) = packh2(cc[0], cc[1]);
                    *(uint32_t*)(dst + o0 + 512) = packh2(cc[2], cc[3]);  // row s+8
                } else {
                    size_t o0 = ((size_t)(b * 8 + h) * 64 + d) * 2048 + s;
                    g_vh[o0] = __float2half_rn(cc[0]);
                    g_vh[o0 + 2048] = __float2half_rn(cc[1]);
                    g_vh[o0 + 8] = __float2half_rn(cc[2]);
                    g_vh[o0 + 2056] = __float2half_rn(cc[3]);
                }
            }
        }
    });
}

// =====================================================================
// Kernel 3: output projection. Epilogue -> fp32 out.
// =====================================================================
__global__ __launch_bounds__(256, 2) void k_out(float* __restrict__ out) {
    const int tid = threadIdx.x, lid = tid & 31, w = tid >> 5;
    const int wm = w >> 1, wn = w & 1;
    const int m0 = blockIdx.x * 128, n0 = blockIdx.y * 64;
    const int g = lid >> 2, t = lid & 3;

    proj_gemm(g_oh, g_ol, g_wh + 3u * 262144, m0, n0, [&](float acc[2][4][4]) {
#pragma unroll
        for (int mf = 0; mf < 2; mf++) {
            int m = m0 + wm * 32 + mf * 16 + g;
#pragma unroll
            for (int nf = 0; nf < 4; nf++) {
                int n = n0 + wn * 32 + nf * 8 + 2 * t;
                float* cc = acc[mf][nf];
                *(float2*)(out + (size_t)m * 512 + n) = make_float2(cc[0], cc[1]);
                *(float2*)(out + (size_t)(m + 8) * 512 + n) = make_float2(cc[2], cc[3]);
            }
        }
    });
}

// =====================================================================
// Kernel 2: fused sigmoid attention. 256 thr, q-tile 128 (8 warps x 16
// rows), 2 CTAs/SM, 3-stage cp.async ring over kv tiles.
// stage layout (elems): K [0,9216) V [9216,17920)
// =====================================================================
constexpr int KST = 72;                    // K-tile smem stride (elems)
constexpr int VST = 136;                   // V-tile smem stride (elems)
constexpr int TST = 17920;                 // stage elems
constexpr int ATTN_SMEM = 3 * TST * 2;     // 107520 B

__global__ __launch_bounds__(256, 2) void k_attn() {
    extern __shared__ __half dsm[];
    const uint32_t u0 = smem_u32(dsm);
    const int tid = threadIdx.x, lid = tid & 31, w = tid >> 5;
    const int q0 = blockIdx.x * 128, bh = blockIdx.y;
    const int g = lid >> 2, t = lid & 3;
    const size_t qkBase = (size_t)bh * 2048 * 64;
    const size_t vBase = (size_t)bh * 131072;

    auto load_stage = [&](int j, int s) {
        uint32_t base = u0 + (uint32_t)(s * TST * 2);
        {   // K: 128 rows x 64 cols
            const int r0 = tid >> 3, q = tid & 7;
#pragma unroll
            for (int it = 0; it < 4; it++) {
                int r = r0 + it * 32;
                size_t src = qkBase + (size_t)(j * 128 + r) * 64 + q * 8;
                cp16(base + (uint32_t)((r * KST + q * 8) * 2), g_kh + src);
            }
        }
        {   // V: 64 rows x 128 cols
            const int r0 = tid >> 4, q = tid & 15;
#pragma unroll
            for (int it = 0; it < 4; it++) {
                int r = r0 + it * 16;
                size_t src = vBase + (size_t)j * 128 + (size_t)r * 2048 + q * 8;
                cp16(base + 18432 + (uint32_t)((r * VST + q * 8) * 2), g_vh + src);
            }
        }
    };

    load_stage(0, 0); cp_commit();
    load_stage(1, 1); cp_commit();

    // Q fragments (fp16) for this warp's 16 rows (resident whole kernel)
    uint32_t qf[4][4];
    {
        const __half* Q = g_qh + qkBase + (size_t)(q0 + w * 16) * 64;
#pragma unroll
        for (int kk = 0; kk < 4; kk++) {
            int c0 = kk * 16 + 2 * t;
            qf[kk][0] = *(const uint32_t*)(Q + g * 64 + c0);
            qf[kk][1] = *(const uint32_t*)(Q + (g + 8) * 64 + c0);
            qf[kk][2] = *(const uint32_t*)(Q + g * 64 + c0 + 8);
            qf[kk][3] = *(const uint32_t*)(Q + (g + 8) * 64 + c0 + 8);
        }
    }

    float oacc[8][4];
#pragma unroll
    for (int nf = 0; nf < 8; nf++)
#pragma unroll
        for (int e = 0; e < 4; e++) oacc[nf][e] = 0.0f;

    for (int j = 0; j < 16; j++) {
        if (j < 15) cp_wait<1>(); else cp_wait<0>();
        __syncthreads();
        if (j < 14) { load_stage(j + 2, (j + 2) % 3); cp_commit(); }

        const uint32_t base = u0 + (uint32_t)((j % 3) * TST * 2);
        const uint32_t uK = base, uV = base + 18432;

        // process S in 4 chunks of 32 columns; PV for that chunk immediately
#pragma unroll
        for (int ck = 0; ck < 4; ck++) {
            float sacc[4][4];
#pragma unroll
            for (int nfl = 0; nfl < 4; nfl++)
#pragma unroll
                for (int e = 0; e < 4; e++) sacc[nfl][e] = 0.0f;

#pragma unroll
            for (int nfl = 0; nfl < 4; nfl++) {
                const int nf = ck * 4 + nfl;
                uint32_t kf[8];
                uint32_t b0 = (uint32_t)((nf * 8 + (lid & 7)) * KST + (lid >> 3) * 8);
                ldsm4(kf, uK + b0 * 2);
                ldsm4(kf + 4, uK + (b0 + 32) * 2);
#pragma unroll
                for (int kk = 0; kk < 4; kk++) mma_f16(sacc[nfl], qf[kk], kf + 2 * kk);
            }

            // sigmoid (single-MUFU tanh path) + pack P fragments
            uint32_t ph[2][4];
#pragma unroll
            for (int u = 0; u < 2; u++) {
                float* s0 = sacc[2 * u];
                float* s1 = sacc[2 * u + 1];
                ph[u][0] = packh2(sigmoid_tanh(s0[0]), sigmoid_tanh(s0[1]));
                ph[u][1] = packh2(sigmoid_tanh(s0[2]), sigmoid_tanh(s0[3]));
                ph[u][2] = packh2(sigmoid_tanh(s1[0]), sigmoid_tanh(s1[1]));
                ph[u][3] = packh2(sigmoid_tanh(s1[2]), sigmoid_tanh(s1[3]));
            }

            // O += P @ V for this k-chunk
#pragma unroll
            for (int nf = 0; nf < 8; nf++) {
                uint32_t vf[4];
                uint32_t o0 =
                    (uint32_t)(((nf * 8 + (lid & 7)) * VST + ck * 32 + (lid >> 3) * 8) * 2);
                ldsm4(vf, uV + o0);
                mma_f16(oacc[nf], ph[0], vf);
                mma_f16(oacc[nf], ph[1], vf + 2);
            }
        }
    }

    // epilogue: split O -> AO scratch fp16 hi/lo [8192, 512]
    {
        const int b = bh >> 3, h = bh & 7;
        const int s = q0 + w * 16 + g;
#pragma unroll
        for (int nf = 0; nf < 8; nf++) {
            int d = nf * 8 + 2 * t;
            uint32_t h01, l01, h23, l23;
            splitpackh(oacc[nf][0], oacc[nf][1], h01, l01);
            splitpackh(oacc[nf][2], oacc[nf][3], h23, l23);
            size_t o0 = ((size_t)b * 2048 + s) * 512 + h * 64 + d;
            *(uint32_t*)(g_oh + o0) = h01;
            *(uint32_t*)(g_ol + o0) = l01;
            size_t o1 = o0 + 8 * 512;
            *(uint32_t*)(g_oh + o1) = h23;
            *(uint32_t*)(g_ol + o1) = l23;
        }
    }
}

// =====================================================================
extern "C" void kernel_launch(void* const* d_in, const int* in_sizes, int n_in,
                              void* d_out, int out_size) {
    const float* x = (const float*)d_in[0];
    const float* Wq = (const float*)d_in[1];
    const float* Wk = (const float*)d_in[2];
    const float* Wv = (const float*)d_in[3];
    const float* Wo = (const float*)d_in[4];
    float* out = (float*)d_out;

    cudaFuncSetAttribute(k_qkv, cudaFuncAttributeMaxDynamicSharedMemorySize, PROJ_SMEM);
    cudaFuncSetAttribute(k_out, cudaFuncAttributeMaxDynamicSharedMemorySize, PROJ_SMEM);
    cudaFuncSetAttribute(k_attn, cudaFuncAttributeMaxDynamicSharedMemorySize, ATTN_SMEM);

    k_split<<<5120, 256>>>(x, Wq, Wk, Wv, Wo);
    k_qkv<<<dim3(64, 8, 3), 256, PROJ_SMEM>>>();
    k_attn<<<dim3(16, 32), 256, ATTN_SMEM>>>();
    k_out<<<dim3(64, 8), 256, PROJ_SMEM>>>(out);
}

// round 11
// speedup vs baseline: 4.1888x; 1.1936x over previous
#include <cuda_runtime.h>
#include <cuda_bf16.h>
#include <cuda_fp16.h>
#include <stdint.h>

#define DI __device__ __forceinline__

// ---------------- scratch (static device globals; no allocation) ----------------
#define SCR_ELEMS (4u * 8u * 2048u * 64u)  // 4,194,304
__device__ __align__(16) __half g_qh[SCR_ELEMS];      // Q fp16: [B,H,S,D]
__device__ __align__(16) __half g_kh[SCR_ELEMS];      // K fp16: [B,H,S,D]
__device__ __align__(16) __half g_vh[SCR_ELEMS];      // V^T fp16: [B,H,D,S]
__device__ __align__(16) __half g_oh[SCR_ELEMS];      // AO hi fp16: [8192, 512]
__device__ __align__(16) __half g_ol[SCR_ELEMS];      // AO lo fp16: [8192, 512]
__device__ __align__(16) __half g_xh[SCR_ELEMS];      // x fp16: [8192, 512]
__device__ __align__(16) __half g_wh[4u * 262144u];   // Wq,Wk,Wv,Wo fp16

// ---------------- helpers ----------------
DI uint32_t smem_u32(const void* p) {
    uint32_t a;
    asm("{ .reg .u64 t; cvta.to.shared.u64 t, %1; cvt.u32.u64 %0, t; }" : "=r"(a) : "l"(p));
    return a;
}
DI void ldsm4(uint32_t* r, uint32_t a) {
    asm volatile("ldmatrix.sync.aligned.m8n8.x4.shared.b16 {%0,%1,%2,%3}, [%4];"
                 : "=r"(r[0]), "=r"(r[1]), "=r"(r[2]), "=r"(r[3]) : "r"(a));
}
DI void mma_f16(float* c, const uint32_t* a, const uint32_t* b) {
    asm volatile(
        "mma.sync.aligned.m16n8k16.row.col.f32.f16.f16.f32 "
        "{%0,%1,%2,%3}, {%4,%5,%6,%7}, {%8,%9}, {%0,%1,%2,%3};"
        : "+f"(c[0]), "+f"(c[1]), "+f"(c[2]), "+f"(c[3])
        : "r"(a[0]), "r"(a[1]), "r"(a[2]), "r"(a[3]), "r"(b[0]), "r"(b[1]));
}
DI void cp16(uint32_t dst, const void* src) {
    asm volatile("cp.async.cg.shared.global [%0], [%1], 16;" :: "r"(dst), "l"(src));
}
DI void cp_commit() { asm volatile("cp.async.commit_group;" ::: "memory"); }
template <int N> DI void cp_wait() { asm volatile("cp.async.wait_group %0;" :: "n"(N) : "memory"); }

DI uint32_t packh2(float a, float b) {
    __half2 h = __floats2half2_rn(a, b);
    return *reinterpret_cast<uint32_t*>(&h);
}
DI void splitpackh(float f0, float f1, uint32_t& ph, uint32_t& pl) {
    __half2 vh = __floats2half2_rn(f0, f1);
    __half2 vl = __floats2half2_rn(f0 - __half2float(vh.x), f1 - __half2float(vh.y));
    ph = *reinterpret_cast<uint32_t*>(&vh);
    pl = *reinterpret_cast<uint32_t*>(&vl);
}
// sigmoid(qk/8 - log 2048) = 0.5 + 0.5*tanh((qk/8 - log2048)/2)  — single MUFU
DI float sigmoid_tanh(float qk) {
    float t = fmaf(qk, 0.0625f, -3.81230949f);  // qk/16 - log(2048)/2
    float th;
    asm("tanh.approx.f32 %0, %1;" : "=f"(th) : "f"(t));
    return fmaf(th, 0.5f, 0.5f);
}

// =====================================================================
// Kernel 0: pre-convert x and weights to fp16.
// =====================================================================
__global__ __launch_bounds__(256) void k_split(const float* __restrict__ x,
                                               const float* __restrict__ Wq,
                                               const float* __restrict__ Wk,
                                               const float* __restrict__ Wv,
                                               const float* __restrict__ Wo) {
    size_t idx = (size_t)blockIdx.x * 256 + threadIdx.x;
    if (idx < 1048576) {
        float4 f = ((const float4*)x)[idx];
        ((uint2*)g_xh)[idx] = make_uint2(packh2(f.x, f.y), packh2(f.z, f.w));
    } else {
        size_t r = idx - 1048576;
        int ws = (int)(r >> 16);
        size_t off = r & 65535;
        const float* src = (ws == 0) ? Wq : (ws == 1) ? Wk : (ws == 2) ? Wv : Wo;
        float4 f = ((const float4*)src)[off];
        ((uint2*)(g_wh + (size_t)ws * 262144))[off] =
            make_uint2(packh2(f.x, f.y), packh2(f.z, f.w));
    }
}

// =====================================================================
// Shared proj-GEMM: BM=128 BN=64 BK=64, 256 thr (8 warps 4m x 2n),
// 2-stage cp.async ring, DUAL toggles (Ah + Al)@B vs Ah@B.
// stage elems: DUAL ? 23040 : 13824
//   layout: A_hi [0,9216) [A_lo 9216,18432 if DUAL) B [last 4608)
// =====================================================================
constexpr int RST = 72;  // padded row stride (elems) for 64-col tiles

template <bool DUAL, typename EPI>
DI void proj_gemm(const __half* __restrict__ Ah, const __half* __restrict__ Al,
                  const __half* __restrict__ B, int m0, int n0, EPI epi) {
    constexpr int PST = DUAL ? 23040 : 13824;
    constexpr uint32_t BOFF = DUAL ? 36864u : 18432u;  // byte offset of B in stage
    extern __shared__ __half dsm[];
    const uint32_t u0 = smem_u32(dsm);
    const int tid = threadIdx.x, lid = tid & 31, w = tid >> 5;
    const int wm = w >> 1, wn = w & 1;

    auto load_stage = [&](int c, int s) {
        uint32_t base = u0 + (uint32_t)(s * PST * 2);
        const int r0 = tid >> 3, q = tid & 7;
#pragma unroll
        for (int it = 0; it < 4; it++) {
            int r = r0 + it * 32;
            size_t src = (size_t)(m0 + r) * 512 + c * 64 + q * 8;
            uint32_t d = (uint32_t)((r * RST + q * 8) * 2);
            cp16(base + d, Ah + src);
            if (DUAL) cp16(base + 18432 + d, Al + src);
        }
#pragma unroll
        for (int it = 0; it < 2; it++) {
            int r = r0 + it * 32;
            size_t src = (size_t)(n0 + r) * 512 + c * 64 + q * 8;
            cp16(base + BOFF + (uint32_t)((r * RST + q * 8) * 2), B + src);
        }
    };

    float acc[2][4][4];
#pragma unroll
    for (int mf = 0; mf < 2; mf++)
#pragma unroll
        for (int nf = 0; nf < 4; nf++)
#pragma unroll
            for (int e = 0; e < 4; e++) acc[mf][nf][e] = 0.0f;

    load_stage(0, 0);
    cp_commit();

    for (int c = 0; c < 8; c++) {
        cp_wait<0>();
        __syncthreads();
        if (c < 7) { load_stage(c + 1, (c + 1) & 1); cp_commit(); }

        const uint32_t bA = u0 + (uint32_t)((c & 1) * PST * 2);
        const uint32_t uAh = bA, uAl = bA + 18432, uB = bA + BOFF;

#pragma unroll
        for (int kh = 0; kh < 2; kh++) {
            uint32_t ah[2][2][4], al[2][2][4];
#pragma unroll
            for (int mf = 0; mf < 2; mf++)
#pragma unroll
                for (int kk = 0; kk < 2; kk++) {
                    uint32_t off = (uint32_t)(((wm * 32 + mf * 16 + (lid & 15)) * RST +
                                               kh * 32 + kk * 16 + (lid >> 4) * 8) * 2);
                    ldsm4(ah[mf][kk], uAh + off);
                    if (DUAL) ldsm4(al[mf][kk], uAl + off);
                }
#pragma unroll
            for (int nf = 0; nf < 4; nf++) {
                uint32_t bf[4];
                uint32_t off = (uint32_t)(((wn * 32 + nf * 8 + (lid & 7)) * RST +
                                           kh * 32 + (lid >> 3) * 8) * 2);
                ldsm4(bf, uB + off);
#pragma unroll
                for (int mf = 0; mf < 2; mf++)
#pragma unroll
                    for (int kk = 0; kk < 2; kk++) {
                        mma_f16(acc[mf][nf], ah[mf][kk], bf + kk * 2);
                        if (DUAL) mma_f16(acc[mf][nf], al[mf][kk], bf + kk * 2);
                    }
            }
        }
    }
    epi(acc);
}

constexpr int QKV_SMEM = 2 * 13824 * 2;  // 55296 B
constexpr int OUT_SMEM = 2 * 23040 * 2;  // 92160 B

// =====================================================================
// Kernel 1: QKV projection (z selects W). Single-combo x_fp16 @ W_fp16.
// =====================================================================
__global__ __launch_bounds__(256, 3) void k_qkv() {
    const int tid = threadIdx.x, lid = tid & 31, w = tid >> 5;
    const int wm = w >> 1, wn = w & 1;
    const int m0 = blockIdx.x * 128, n0 = blockIdx.y * 64, z = blockIdx.z;
    const int g = lid >> 2, t = lid & 3;

    proj_gemm<false>(g_xh, nullptr, g_wh + (size_t)z * 262144, m0, n0,
                     [&](float acc[2][4][4]) {
#pragma unroll
        for (int mf = 0; mf < 2; mf++) {
            int m = m0 + wm * 32 + mf * 16 + g;
            int b = m >> 11, s = m & 2047;
#pragma unroll
            for (int nf = 0; nf < 4; nf++) {
                int n = n0 + wn * 32 + nf * 8 + 2 * t;
                int h = n >> 6, d = n & 63;
                float* cc = acc[mf][nf];
                if (z < 2) {
                    __half* dst = (z == 0) ? g_qh : g_kh;
                    size_t o0 = ((size_t)(b * 8 + h) * 2048 + s) * 64 + d;
                    *(uint32_t*)(dst + o0) = packh2(cc[0], cc[1]);
                    *(uint32_t*)(dst + o0 + 512) = packh2(cc[2], cc[3]);  // row s+8
                } else {
                    size_t o0 = ((size_t)(b * 8 + h) * 64 + d) * 2048 + s;
                    g_vh[o0] = __float2half_rn(cc[0]);
                    g_vh[o0 + 2048] = __float2half_rn(cc[1]);
                    g_vh[o0 + 8] = __float2half_rn(cc[2]);
                    g_vh[o0 + 2056] = __float2half_rn(cc[3]);
                }
            }
        }
    });
}

// =====================================================================
// Kernel 3: output projection. 2-combo (AOh + AOl) @ Wo_fp16 -> fp32.
// =====================================================================
__global__ __launch_bounds__(256, 2) void k_out(float* __restrict__ out) {
    const int tid = threadIdx.x, lid = tid & 31, w = tid >> 5;
    const int wm = w >> 1, wn = w & 1;
    const int m0 = blockIdx.x * 128, n0 = blockIdx.y * 64;
    const int g = lid >> 2, t = lid & 3;

    proj_gemm<true>(g_oh, g_ol, g_wh + 3u * 262144, m0, n0, [&](float acc[2][4][4]) {
#pragma unroll
        for (int mf = 0; mf < 2; mf++) {
            int m = m0 + wm * 32 + mf * 16 + g;
#pragma unroll
            for (int nf = 0; nf < 4; nf++) {
                int n = n0 + wn * 32 + nf * 8 + 2 * t;
                float* cc = acc[mf][nf];
                *(float2*)(out + (size_t)m * 512 + n) = make_float2(cc[0], cc[1]);
                *(float2*)(out + (size_t)(m + 8) * 512 + n) = make_float2(cc[2], cc[3]);
            }
        }
    });
}

// =====================================================================
// Kernel 2: fused sigmoid attention. 256 thr, q-tile 128 (8 warps x 16
// rows), 2 CTAs/SM, 3-stage cp.async ring over kv tiles.
// stage layout (elems): K [0,9216) V [9216,17920)
// =====================================================================
constexpr int KST = 72;                    // K-tile smem stride (elems)
constexpr int VST = 136;                   // V-tile smem stride (elems)
constexpr int TST = 17920;                 // stage elems
constexpr int ATTN_SMEM = 3 * TST * 2;     // 107520 B

__global__ __launch_bounds__(256, 2) void k_attn() {
    extern __shared__ __half dsm[];
    const uint32_t u0 = smem_u32(dsm);
    const int tid = threadIdx.x, lid = tid & 31, w = tid >> 5;
    const int q0 = blockIdx.x * 128, bh = blockIdx.y;
    const int g = lid >> 2, t = lid & 3;
    const size_t qkBase = (size_t)bh * 2048 * 64;
    const size_t vBase = (size_t)bh * 131072;

    auto load_stage = [&](int j, int s) {
        uint32_t base = u0 + (uint32_t)(s * TST * 2);
        {   // K: 128 rows x 64 cols
            const int r0 = tid >> 3, q = tid & 7;
#pragma unroll
            for (int it = 0; it < 4; it++) {
                int r = r0 + it * 32;
                size_t src = qkBase + (size_t)(j * 128 + r) * 64 + q * 8;
                cp16(base + (uint32_t)((r * KST + q * 8) * 2), g_kh + src);
            }
        }
        {   // V: 64 rows x 128 cols
            const int r0 = tid >> 4, q = tid & 15;
#pragma unroll
            for (int it = 0; it < 4; it++) {
                int r = r0 + it * 16;
                size_t src = vBase + (size_t)j * 128 + (size_t)r * 2048 + q * 8;
                cp16(base + 18432 + (uint32_t)((r * VST + q * 8) * 2), g_vh + src);
            }
        }
    };

    load_stage(0, 0); cp_commit();
    load_stage(1, 1); cp_commit();

    // Q fragments (fp16) for this warp's 16 rows (resident whole kernel)
    uint32_t qf[4][4];
    {
        const __half* Q = g_qh + qkBase + (size_t)(q0 + w * 16) * 64;
#pragma unroll
        for (int kk = 0; kk < 4; kk++) {
            int c0 = kk * 16 + 2 * t;
            qf[kk][0] = *(const uint32_t*)(Q + g * 64 + c0);
            qf[kk][1] = *(const uint32_t*)(Q + (g + 8) * 64 + c0);
            qf[kk][2] = *(const uint32_t*)(Q + g * 64 + c0 + 8);
            qf[kk][3] = *(const uint32_t*)(Q + (g + 8) * 64 + c0 + 8);
        }
    }

    float oacc[8][4];
#pragma unroll
    for (int nf = 0; nf < 8; nf++)
#pragma unroll
        for (int e = 0; e < 4; e++) oacc[nf][e] = 0.0f;

    for (int j = 0; j < 16; j++) {
        if (j < 15) cp_wait<1>(); else cp_wait<0>();
        __syncthreads();
        if (j < 14) { load_stage(j + 2, (j + 2) % 3); cp_commit(); }

        const uint32_t base = u0 + (uint32_t)((j % 3) * TST * 2);
        const uint32_t uK = base, uV = base + 18432;

        // process S in 4 chunks of 32 columns; PV for that chunk immediately
#pragma unroll
        for (int ck = 0; ck < 4; ck++) {
            float sacc[4][4];
#pragma unroll
            for (int nfl = 0; nfl < 4; nfl++)
#pragma unroll
                for (int e = 0; e < 4; e++) sacc[nfl][e] = 0.0f;

#pragma unroll
            for (int nfl = 0; nfl < 4; nfl++) {
                const int nf = ck * 4 + nfl;
                uint32_t kf[8];
                uint32_t b0 = (uint32_t)((nf * 8 + (lid & 7)) * KST + (lid >> 3) * 8);
                ldsm4(kf, uK + b0 * 2);
                ldsm4(kf + 4, uK + (b0 + 32) * 2);
#pragma unroll
                for (int kk = 0; kk < 4; kk++) mma_f16(sacc[nfl], qf[kk], kf + 2 * kk);
            }

            // sigmoid (single-MUFU tanh path) + pack P fragments
            uint32_t ph[2][4];
#pragma unroll
            for (int u = 0; u < 2; u++) {
                float* s0 = sacc[2 * u];
                float* s1 = sacc[2 * u + 1];
                ph[u][0] = packh2(sigmoid_tanh(s0[0]), sigmoid_tanh(s0[1]));
                ph[u][1] = packh2(sigmoid_tanh(s0[2]), sigmoid_tanh(s0[3]));
                ph[u][2] = packh2(sigmoid_tanh(s1[0]), sigmoid_tanh(s1[1]));
                ph[u][3] = packh2(sigmoid_tanh(s1[2]), sigmoid_tanh(s1[3]));
            }

            // O += P @ V for this k-chunk
#pragma unroll
            for (int nf = 0; nf < 8; nf++) {
                uint32_t vf[4];
                uint32_t o0 =
                    (uint32_t)(((nf * 8 + (lid & 7)) * VST + ck * 32 + (lid >> 3) * 8) * 2);
                ldsm4(vf, uV + o0);
                mma_f16(oacc[nf], ph[0], vf);
                mma_f16(oacc[nf], ph[1], vf + 2);
            }
        }
    }

    // epilogue: split O -> AO scratch fp16 hi/lo [8192, 512]
    {
        const int b = bh >> 3, h = bh & 7;
        const int s = q0 + w * 16 + g;
#pragma unroll
        for (int nf = 0; nf < 8; nf++) {
            int d = nf * 8 + 2 * t;
            uint32_t h01, l01, h23, l23;
            splitpackh(oacc[nf][0], oacc[nf][1], h01, l01);
            splitpackh(oacc[nf][2], oacc[nf][3], h23, l23);
            size_t o0 = ((size_t)b * 2048 + s) * 512 + h * 64 + d;
            *(uint32_t*)(g_oh + o0) = h01;
            *(uint32_t*)(g_ol + o0) = l01;
            size_t o1 = o0 + 8 * 512;
            *(uint32_t*)(g_oh + o1) = h23;
            *(uint32_t*)(g_ol + o1) = l23;
        }
    }
}

// =====================================================================
extern "C" void kernel_launch(void* const* d_in, const int* in_sizes, int n_in,
                              void* d_out, int out_size) {
    const float* x = (const float*)d_in[0];
    const float* Wq = (const float*)d_in[1];
    const float* Wk = (const float*)d_in[2];
    const float* Wv = (const float*)d_in[3];
    const float* Wo = (const float*)d_in[4];
    float* out = (float*)d_out;

    cudaFuncSetAttribute(k_qkv, cudaFuncAttributeMaxDynamicSharedMemorySize, QKV_SMEM);
    cudaFuncSetAttribute(k_out, cudaFuncAttributeMaxDynamicSharedMemorySize, OUT_SMEM);
    cudaFuncSetAttribute(k_attn, cudaFuncAttributeMaxDynamicSharedMemorySize, ATTN_SMEM);

    k_split<<<5120, 256>>>(x, Wq, Wk, Wv, Wo);
    k_qkv<<<dim3(64, 8, 3), 256, QKV_SMEM>>>();
    k_attn<<<dim3(16, 32), 256, ATTN_SMEM>>>();
    k_out<<<dim3(64, 8), 256, OUT_SMEM>>>(out);
}

// round 12
// speedup vs baseline: 4.5744x; 1.0921x over previous
#include <cuda_runtime.h>
#include <cuda_bf16.h>
#include <cuda_fp16.h>
#include <stdint.h>

#define DI __device__ __forceinline__

// ---------------- scratch (static device globals; no allocation) ----------------
#define SCR_ELEMS (4u * 8u * 2048u * 64u)  // 4,194,304
__device__ __align__(16) __half g_qh[SCR_ELEMS];      // Q fp16: [B,H,S,D]
__device__ __align__(16) __half g_kh[SCR_ELEMS];      // K fp16: [B,H,S,D]
__device__ __align__(16) __half g_vh[SCR_ELEMS];      // V^T fp16: [B,H,D,S]
__device__ __align__(16) __half g_oh[SCR_ELEMS];      // AO fp16: [8192, 512]
__device__ __align__(16) __half g_xh[SCR_ELEMS];      // x fp16: [8192, 512]
__device__ __align__(16) __half g_wh[4u * 262144u];   // Wq,Wk,Wv,Wo fp16

// ---------------- helpers ----------------
DI uint32_t smem_u32(const void* p) {
    uint32_t a;
    asm("{ .reg .u64 t; cvta.to.shared.u64 t, %1; cvt.u32.u64 %0, t; }" : "=r"(a) : "l"(p));
    return a;
}
DI void ldsm4(uint32_t* r, uint32_t a) {
    asm volatile("ldmatrix.sync.aligned.m8n8.x4.shared.b16 {%0,%1,%2,%3}, [%4];"
                 : "=r"(r[0]), "=r"(r[1]), "=r"(r[2]), "=r"(r[3]) : "r"(a));
}
DI void mma_f16(float* c, const uint32_t* a, const uint32_t* b) {
    asm volatile(
        "mma.sync.aligned.m16n8k16.row.col.f32.f16.f16.f32 "
        "{%0,%1,%2,%3}, {%4,%5,%6,%7}, {%8,%9}, {%0,%1,%2,%3};"
        : "+f"(c[0]), "+f"(c[1]), "+f"(c[2]), "+f"(c[3])
        : "r"(a[0]), "r"(a[1]), "r"(a[2]), "r"(a[3]), "r"(b[0]), "r"(b[1]));
}
DI void cp16(uint32_t dst, const void* src) {
    asm volatile("cp.async.cg.shared.global [%0], [%1], 16;" :: "r"(dst), "l"(src));
}
DI void cp_commit() { asm volatile("cp.async.commit_group;" ::: "memory"); }
template <int N> DI void cp_wait() { asm volatile("cp.async.wait_group %0;" :: "n"(N) : "memory"); }

DI uint32_t packh2(float a, float b) {
    __half2 h = __floats2half2_rn(a, b);
    return *reinterpret_cast<uint32_t*>(&h);
}
// sigmoid(qk/8 - log 2048) = 0.5 + 0.5*tanh((qk/8 - log2048)/2)  — single MUFU
DI float sigmoid_tanh(float qk) {
    float t = fmaf(qk, 0.0625f, -3.81230949f);  // qk/16 - log(2048)/2
    float th;
    asm("tanh.approx.f32 %0, %1;" : "=f"(th) : "f"(t));
    return fmaf(th, 0.5f, 0.5f);
}

// =====================================================================
// Kernel 0: pre-convert x and weights to fp16.
// =====================================================================
__global__ __launch_bounds__(256) void k_split(const float* __restrict__ x,
                                               const float* __restrict__ Wq,
                                               const float* __restrict__ Wk,
                                               const float* __restrict__ Wv,
                                               const float* __restrict__ Wo) {
    size_t idx = (size_t)blockIdx.x * 256 + threadIdx.x;
    if (idx < 1048576) {
        float4 f = ((const float4*)x)[idx];
        ((uint2*)g_xh)[idx] = make_uint2(packh2(f.x, f.y), packh2(f.z, f.w));
    } else {
        size_t r = idx - 1048576;
        int ws = (int)(r >> 16);
        size_t off = r & 65535;
        const float* src = (ws == 0) ? Wq : (ws == 1) ? Wk : (ws == 2) ? Wv : Wo;
        float4 f = ((const float4*)src)[off];
        ((uint2*)(g_wh + (size_t)ws * 262144))[off] =
            make_uint2(packh2(f.x, f.y), packh2(f.z, f.w));
    }
}

// =====================================================================
// Shared proj-GEMM: BM=128 BN=64 BK=64, 256 thr (8 warps 4m x 2n),
// 2-stage cp.async ring, single-combo A_fp16 @ B_fp16.
// stage elems: 13824.  layout: A [0,9216) B [9216,13824)
// =====================================================================
constexpr int RST = 72;   // padded row stride (elems) for 64-col tiles
constexpr int PST = 13824;
constexpr int PROJ_SMEM = 2 * PST * 2;  // 55296 B

template <typename EPI>
DI void proj_gemm(const __half* __restrict__ A, const __half* __restrict__ B,
                  int m0, int n0, EPI epi) {
    extern __shared__ __half dsm[];
    const uint32_t u0 = smem_u32(dsm);
    const int tid = threadIdx.x, lid = tid & 31, w = tid >> 5;
    const int wm = w >> 1, wn = w & 1;

    auto load_stage = [&](int c, int s) {
        uint32_t base = u0 + (uint32_t)(s * PST * 2);
        const int r0 = tid >> 3, q = tid & 7;
#pragma unroll
        for (int it = 0; it < 4; it++) {
            int r = r0 + it * 32;
            size_t src = (size_t)(m0 + r) * 512 + c * 64 + q * 8;
            cp16(base + (uint32_t)((r * RST + q * 8) * 2), A + src);
        }
#pragma unroll
        for (int it = 0; it < 2; it++) {
            int r = r0 + it * 32;
            size_t src = (size_t)(n0 + r) * 512 + c * 64 + q * 8;
            cp16(base + 18432u + (uint32_t)((r * RST + q * 8) * 2), B + src);
        }
    };

    float acc[2][4][4];
#pragma unroll
    for (int mf = 0; mf < 2; mf++)
#pragma unroll
        for (int nf = 0; nf < 4; nf++)
#pragma unroll
            for (int e = 0; e < 4; e++) acc[mf][nf][e] = 0.0f;

    load_stage(0, 0);
    cp_commit();

    for (int c = 0; c < 8; c++) {
        cp_wait<0>();
        __syncthreads();
        if (c < 7) { load_stage(c + 1, (c + 1) & 1); cp_commit(); }

        const uint32_t bA = u0 + (uint32_t)((c & 1) * PST * 2);
        const uint32_t uA = bA, uB = bA + 18432u;

#pragma unroll
        for (int kh = 0; kh < 2; kh++) {
            uint32_t af[2][2][4];
#pragma unroll
            for (int mf = 0; mf < 2; mf++)
#pragma unroll
                for (int kk = 0; kk < 2; kk++) {
                    uint32_t off = (uint32_t)(((wm * 32 + mf * 16 + (lid & 15)) * RST +
                                               kh * 32 + kk * 16 + (lid >> 4) * 8) * 2);
                    ldsm4(af[mf][kk], uA + off);
                }
#pragma unroll
            for (int nf = 0; nf < 4; nf++) {
                uint32_t bf[4];
                uint32_t off = (uint32_t)(((wn * 32 + nf * 8 + (lid & 7)) * RST +
                                           kh * 32 + (lid >> 3) * 8) * 2);
                ldsm4(bf, uB + off);
#pragma unroll
                for (int mf = 0; mf < 2; mf++)
#pragma unroll
                    for (int kk = 0; kk < 2; kk++)
                        mma_f16(acc[mf][nf], af[mf][kk], bf + kk * 2);
            }
        }
    }
    epi(acc);
}

// =====================================================================
// Kernel 1: QKV projection (z selects W). Epilogue -> Q/K fp16, V^T fp16.
// =====================================================================
__global__ __launch_bounds__(256, 3) void k_qkv() {
    const int tid = threadIdx.x, lid = tid & 31, w = tid >> 5;
    const int wm = w >> 1, wn = w & 1;
    const int m0 = blockIdx.x * 128, n0 = blockIdx.y * 64, z = blockIdx.z;
    const int g = lid >> 2, t = lid & 3;

    proj_gemm(g_xh, g_wh + (size_t)z * 262144, m0, n0, [&](float acc[2][4][4]) {
#pragma unroll
        for (int mf = 0; mf < 2; mf++) {
            int m = m0 + wm * 32 + mf * 16 + g;
            int b = m >> 11, s = m & 2047;
#pragma unroll
            for (int nf = 0; nf < 4; nf++) {
                int n = n0 + wn * 32 + nf * 8 + 2 * t;
                int h = n >> 6, d = n & 63;
                float* cc = acc[mf][nf];
                if (z < 2) {
                    __half* dst = (z == 0) ? g_qh : g_kh;
                    size_t o0 = ((size_t)(b * 8 + h) * 2048 + s) * 64 + d;
                    *(uint32_t*)(dst + o0) = packh2(cc[0], cc[1]);
                    *(uint32_t*)(dst + o0 + 512) = packh2(cc[2], cc[3]);  // row s+8
                } else {
                    size_t o0 = ((size_t)(b * 8 + h) * 64 + d) * 2048 + s;
                    g_vh[o0] = __float2half_rn(cc[0]);
                    g_vh[o0 + 2048] = __float2half_rn(cc[1]);
                    g_vh[o0 + 8] = __float2half_rn(cc[2]);
                    g_vh[o0 + 2056] = __float2half_rn(cc[3]);
                }
            }
        }
    });
}

// =====================================================================
// Kernel 3: output projection. Single-combo AO_fp16 @ Wo_fp16 -> fp32.
// =====================================================================
__global__ __launch_bounds__(256, 3) void k_out(float* __restrict__ out) {
    const int tid = threadIdx.x, lid = tid & 31, w = tid >> 5;
    const int wm = w >> 1, wn = w & 1;
    const int m0 = blockIdx.x * 128, n0 = blockIdx.y * 64;
    const int g = lid >> 2, t = lid & 3;

    proj_gemm(g_oh, g_wh + 3u * 262144, m0, n0, [&](float acc[2][4][4]) {
#pragma unroll
        for (int mf = 0; mf < 2; mf++) {
            int m = m0 + wm * 32 + mf * 16 + g;
#pragma unroll
            for (int nf = 0; nf < 4; nf++) {
                int n = n0 + wn * 32 + nf * 8 + 2 * t;
                float* cc = acc[mf][nf];
                *(float2*)(out + (size_t)m * 512 + n) = make_float2(cc[0], cc[1]);
                *(float2*)(out + (size_t)(m + 8) * 512 + n) = make_float2(cc[2], cc[3]);
            }
        }
    });
}

// =====================================================================
// Kernel 2: fused sigmoid attention. 256 thr, q-tile 128 (8 warps x 16
// rows), 2 CTAs/SM, 3-stage cp.async ring over kv tiles.
// stage layout (elems): K [0,9216) V [9216,17920)
// =====================================================================
constexpr int KST = 72;                    // K-tile smem stride (elems)
constexpr int VST = 136;                   // V-tile smem stride (elems)
constexpr int TST = 17920;                 // stage elems
constexpr int ATTN_SMEM = 3 * TST * 2;     // 107520 B

__global__ __launch_bounds__(256, 2) void k_attn() {
    extern __shared__ __half dsm[];
    const uint32_t u0 = smem_u32(dsm);
    const int tid = threadIdx.x, lid = tid & 31, w = tid >> 5;
    const int q0 = blockIdx.x * 128, bh = blockIdx.y;
    const int g = lid >> 2, t = lid & 3;
    const size_t qkBase = (size_t)bh * 2048 * 64;
    const size_t vBase = (size_t)bh * 131072;

    auto load_stage = [&](int j, int s) {
        uint32_t base = u0 + (uint32_t)(s * TST * 2);
        {   // K: 128 rows x 64 cols
            const int r0 = tid >> 3, q = tid & 7;
#pragma unroll
            for (int it = 0; it < 4; it++) {
                int r = r0 + it * 32;
                size_t src = qkBase + (size_t)(j * 128 + r) * 64 + q * 8;
                cp16(base + (uint32_t)((r * KST + q * 8) * 2), g_kh + src);
            }
        }
        {   // V: 64 rows x 128 cols
            const int r0 = tid >> 4, q = tid & 15;
#pragma unroll
            for (int it = 0; it < 4; it++) {
                int r = r0 + it * 16;
                size_t src = vBase + (size_t)j * 128 + (size_t)r * 2048 + q * 8;
                cp16(base + 18432 + (uint32_t)((r * VST + q * 8) * 2), g_vh + src);
            }
        }
    };

    load_stage(0, 0); cp_commit();
    load_stage(1, 1); cp_commit();

    // Q fragments (fp16) for this warp's 16 rows (resident whole kernel)
    uint32_t qf[4][4];
    {
        const __half* Q = g_qh + qkBase + (size_t)(q0 + w * 16) * 64;
#pragma unroll
        for (int kk = 0; kk < 4; kk++) {
            int c0 = kk * 16 + 2 * t;
            qf[kk][0] = *(const uint32_t*)(Q + g * 64 + c0);
            qf[kk][1] = *(const uint32_t*)(Q + (g + 8) * 64 + c0);
            qf[kk][2] = *(const uint32_t*)(Q + g * 64 + c0 + 8);
            qf[kk][3] = *(const uint32_t*)(Q + (g + 8) * 64 + c0 + 8);
        }
    }

    float oacc[8][4];
#pragma unroll
    for (int nf = 0; nf < 8; nf++)
#pragma unroll
        for (int e = 0; e < 4; e++) oacc[nf][e] = 0.0f;

    for (int j = 0; j < 16; j++) {
        if (j < 15) cp_wait<1>(); else cp_wait<0>();
        __syncthreads();
        if (j < 14) { load_stage(j + 2, (j + 2) % 3); cp_commit(); }

        const uint32_t base = u0 + (uint32_t)((j % 3) * TST * 2);
        const uint32_t uK = base, uV = base + 18432;

        // process S in 4 chunks of 32 columns; PV for that chunk immediately
#pragma unroll
        for (int ck = 0; ck < 4; ck++) {
            float sacc[4][4];
#pragma unroll
            for (int nfl = 0; nfl < 4; nfl++)
#pragma unroll
                for (int e = 0; e < 4; e++) sacc[nfl][e] = 0.0f;

#pragma unroll
            for (int nfl = 0; nfl < 4; nfl++) {
                const int nf = ck * 4 + nfl;
                uint32_t kf[8];
                uint32_t b0 = (uint32_t)((nf * 8 + (lid & 7)) * KST + (lid >> 3) * 8);
                ldsm4(kf, uK + b0 * 2);
                ldsm4(kf + 4, uK + (b0 + 32) * 2);
#pragma unroll
                for (int kk = 0; kk < 4; kk++) mma_f16(sacc[nfl], qf[kk], kf + 2 * kk);
            }

            // sigmoid (single-MUFU tanh path) + pack P fragments
            uint32_t ph[2][4];
#pragma unroll
            for (int u = 0; u < 2; u++) {
                float* s0 = sacc[2 * u];
                float* s1 = sacc[2 * u + 1];
                ph[u][0] = packh2(sigmoid_tanh(s0[0]), sigmoid_tanh(s0[1]));
                ph[u][1] = packh2(sigmoid_tanh(s0[2]), sigmoid_tanh(s0[3]));
                ph[u][2] = packh2(sigmoid_tanh(s1[0]), sigmoid_tanh(s1[1]));
                ph[u][3] = packh2(sigmoid_tanh(s1[2]), sigmoid_tanh(s1[3]));
            }

            // O += P @ V for this k-chunk
#pragma unroll
            for (int nf = 0; nf < 8; nf++) {
                uint32_t vf[4];
                uint32_t o0 =
                    (uint32_t)(((nf * 8 + (lid & 7)) * VST + ck * 32 + (lid >> 3) * 8) * 2);
                ldsm4(vf, uV + o0);
                mma_f16(oacc[nf], ph[0], vf);
                mma_f16(oacc[nf], ph[1], vf + 2);
            }
        }
    }

    // epilogue: O -> AO scratch fp16 [8192, 512]
    {
        const int b = bh >> 3, h = bh & 7;
        const int s = q0 + w * 16 + g;
#pragma unroll
        for (int nf = 0; nf < 8; nf++) {
            int d = nf * 8 + 2 * t;
            size_t o0 = ((size_t)b * 2048 + s) * 512 + h * 64 + d;
            *(uint32_t*)(g_oh + o0) = packh2(oacc[nf][0], oacc[nf][1]);
            *(uint32_t*)(g_oh + o0 + 8 * 512) = packh2(oacc[nf][2], oacc[nf][3]);
        }
    }
}

// =====================================================================
extern "C" void kernel_launch(void* const* d_in, const int* in_sizes, int n_in,
                              void* d_out, int out_size) {
    const float* x = (const float*)d_in[0];
    const float* Wq = (const float*)d_in[1];
    const float* Wk = (const float*)d_in[2];
    const float* Wv = (const float*)d_in[3];
    const float* Wo = (const float*)d_in[4];
    float* out = (float*)d_out;

    cudaFuncSetAttribute(k_qkv, cudaFuncAttributeMaxDynamicSharedMemorySize, PROJ_SMEM);
    cudaFuncSetAttribute(k_out, cudaFuncAttributeMaxDynamicSharedMemorySize, PROJ_SMEM);
    cudaFuncSetAttribute(k_attn, cudaFuncAttributeMaxDynamicSharedMemorySize, ATTN_SMEM);

    k_split<<<5120, 256>>>(x, Wq, Wk, Wv, Wo);
    k_qkv<<<dim3(64, 8, 3), 256, PROJ_SMEM>>>();
    k_attn<<<dim3(16, 32), 256, ATTN_SMEM>>>();
    k_out<<<dim3(64, 8), 256, PROJ_SMEM>>>(out);
}